// round 9
// baseline (speedup 1.0000x reference)
#include <cuda_runtime.h>
#include <math.h>
#include <float.h>

// ---------------------------------------------------------------------------
// EdgeConv-style GNN block:
//   layer1 factorized over nodes:  pre1(e) = A[tgt] + B[src]
//   layer2 fused per-message GEMM (messages counting-sorted by tgt):
//       z = relu(pre1) @ W2'^T + c2   (BN1 folded)
//   epilogue: run-combined max over relu(z+c2), BN2 applied at flush,
//             atomic float max into agg[tgt]
//   layer3: out = BN3(relu(agg @ W3^T + b3))
// ---------------------------------------------------------------------------

#define C_IN   128
#define C_OUT  256
#define TM     64     // k1/k3 rows per CTA
#define TM2    128    // k2 rows per CTA
#define KC     64     // K chunk
#define NTHR   256
#define SVS    65     // k1/k3 float2 row stride
#define SVS2   66     // k2 float2 row stride (16B-aligned rows)
#define BN_EPS 1e-5f
#define MAXN   20000
#define MAXE   640000
#define MAXM   (MAXE + MAXN)

__host__ __device__ __forceinline__ int prow2(int r) { return r * SVS2 + ((r >> 3) << 1); }
#define PROW128 (128 * SVS2 + 32)   // 8480 float2

// ---- static device scratch -------------------------------------------------
static __device__ __align__(128) float g_AB [(size_t)MAXN * 2 * C_OUT];
static __device__ __align__(128) float g_agg[(size_t)MAXN * C_OUT];
static __device__ __align__(128) float g_Wct[C_IN * 2 * C_OUT];
static __device__ __align__(128) float g_W2t[C_OUT * C_OUT];
static __device__ __align__(128) float g_W3t[C_OUT * C_OUT];
static __device__ __align__(128) float g_c2 [C_OUT];
static __device__ __align__(128) float g_s2 [C_OUT], g_t2[C_OUT];
static __device__ __align__(128) float g_s3 [C_OUT], g_t3[C_OUT];
static __device__ __align__(128) int   g_src[MAXE], g_tgt[MAXE];
static __device__ __align__(128) int   g_osrc[MAXM], g_otgt[MAXM];
static __device__ __align__(128) int   g_cnt[MAXN], g_cur[MAXN];
static __device__ int g_idx64;

// ---- packed fp32x2 FMA ------------------------------------------------------
__device__ __forceinline__ unsigned long long fma2(unsigned long long a,
                                                   unsigned long long b,
                                                   unsigned long long c) {
    unsigned long long d;
    asm("fma.rn.f32x2 %0, %1, %2, %3;" : "=l"(d) : "l"(a), "l"(b), "l"(c));
    return d;
}
__device__ __forceinline__ float2 unpack2(unsigned long long u) {
    float2 f;
    asm("mov.b64 {%0, %1}, %2;" : "=f"(f.x), "=f"(f.y) : "l"(u));
    return f;
}
__device__ __forceinline__ void lds_v2u64(unsigned long long& a, unsigned long long& b,
                                          unsigned int addr) {
    asm volatile("ld.shared.v2.u64 {%0, %1}, [%2];" : "=l"(a), "=l"(b) : "r"(addr));
}

__device__ __forceinline__ void atomicMaxF(float* a, float v) {
    int bits = __float_as_int(v);
    if (bits >= 0) atomicMax((int*)a, bits);
    else           atomicMin((unsigned int*)a, (unsigned int)bits);
}

// ---- k1/k3 shared GEMM inner loop (unchanged, known-good) -------------------
__device__ __forceinline__ void gemm_chunk(const float2* __restrict__ sV2,
                                           const float* __restrict__ sW,
                                           unsigned long long acc[8][4],
                                           int mg, int ng) {
    const float2* vbase = sV2 + mg * 8 * SVS;
    const unsigned long long* wbase =
        reinterpret_cast<const unsigned long long*>(sW + ng * 8);
#pragma unroll 4
    for (int k = 0; k < KC; ++k) {
        unsigned long long w0 = wbase[k * 128 + 0];
        unsigned long long w1 = wbase[k * 128 + 1];
        unsigned long long w2 = wbase[k * 128 + 2];
        unsigned long long w3 = wbase[k * 128 + 3];
#pragma unroll
        for (int i = 0; i < 8; ++i) {
            unsigned long long vv =
                *reinterpret_cast<const unsigned long long*>(vbase + i * SVS + k);
            acc[i][0] = fma2(vv, w0, acc[i][0]);
            acc[i][1] = fma2(vv, w1, acc[i][1]);
            acc[i][2] = fma2(vv, w2, acc[i][2]);
            acc[i][3] = fma2(vv, w3, acc[i][3]);
        }
    }
}

__device__ __forceinline__ void load_w_chunk(float* sW, const float* __restrict__ gW,
                                             int rowStride, int tid) {
    for (int t = tid; t < KC * (C_OUT / 4); t += NTHR) {
        int kk = t >> 6;
        int c4 = t & 63;
        *(float4*)(sW + kk * C_OUT + (c4 << 2)) =
            *(const float4*)(gW + (size_t)kk * rowStride + (c4 << 2));
    }
}

// ---- edge index dtype detection + decode ------------------------------------
__global__ void detect_idx(const int* __restrict__ p) {
    if (threadIdx.x == 0) {
        int is64 = 1;
        for (int i = 0; i < 64; ++i)
            if (p[2 * i + 1] != 0) { is64 = 0; break; }
        g_idx64 = is64;
    }
}

__global__ void decode_idx(const void* __restrict__ idxRaw, long long E2, int Nn) {
    long long i = (long long)blockIdx.x * blockDim.x + threadIdx.x;
    if (i >= E2) return;
    int v;
    if (g_idx64) v = (int)((const long long*)idxRaw)[i];
    else         v = ((const int*)idxRaw)[i];
    if (v < 0) v = 0;
    if (v >= Nn) v = Nn - 1;
    long long E = E2 >> 1;
    if (i < E) g_src[i] = v;
    else       g_tgt[i - E] = v;
}

// ---- counting sort by tgt ----------------------------------------------------
__global__ void hist_zero(int Nn) {
    int i = blockIdx.x * blockDim.x + threadIdx.x;
    if (i < Nn) g_cnt[i] = 0;
}
__global__ void hist_tgt(long long E) {
    long long m = (long long)blockIdx.x * blockDim.x + threadIdx.x;
    if (m < E) atomicAdd(&g_cnt[g_tgt[m]], 1);
}
__global__ void scan_base(int Nn) {     // single CTA, 256 threads
    __shared__ int part[256];
    int th = threadIdx.x;
    int chunk = (Nn + 255) >> 8;
    int lo = th * chunk, hi = lo + chunk; if (hi > Nn) hi = Nn; if (lo > Nn) lo = Nn;
    int s = 0;
    for (int n = lo; n < hi; ++n) s += g_cnt[n] + 1;   // +1 self loop
    part[th] = s;
    __syncthreads();
    if (th == 0) {
        int r = 0;
        for (int i = 0; i < 256; ++i) { int t = part[i]; part[i] = r; r += t; }
    }
    __syncthreads();
    int run = part[th];
    for (int n = lo; n < hi; ++n) { g_cur[n] = run; run += g_cnt[n] + 1; }
}
__global__ void scatter_edges(long long E) {
    long long m = (long long)blockIdx.x * blockDim.x + threadIdx.x;
    if (m >= E) return;
    int t = g_tgt[m];
    int p = atomicAdd(&g_cur[t], 1);
    g_osrc[p] = g_src[m];
    g_otgt[p] = t;
}
__global__ void scatter_loops(int Nn) {
    int n = blockIdx.x * blockDim.x + threadIdx.x;
    if (n >= Nn) return;
    int p = atomicAdd(&g_cur[n], 1);
    g_osrc[p] = n;
    g_otgt[p] = n;
}

// ---- prep kernels -----------------------------------------------------------
__global__ void prep_bn(const float* g1, const float* be1, const float* m1, const float* v1,
                        const float* W2, const float* b2,
                        const float* g2, const float* be2, const float* m2, const float* v2,
                        const float* g3, const float* be3, const float* m3, const float* v3) {
    int c = threadIdx.x;
    float s2 = g2[c] * rsqrtf(v2[c] + BN_EPS);
    g_s2[c] = s2;  g_t2[c] = be2[c] - m2[c] * s2;
    float s3 = g3[c] * rsqrtf(v3[c] + BN_EPS);
    g_s3[c] = s3;  g_t3[c] = be3[c] - m3[c] * s3;
    float acc = b2[c];
    for (int k = 0; k < C_OUT; ++k) {
        float s1 = g1[k] * rsqrtf(v1[k] + BN_EPS);
        float t1 = be1[k] - m1[k] * s1;
        acc += W2[c * C_OUT + k] * t1;
    }
    g_c2[c] = acc;
}

__global__ void prep_w(const float* W1, const float* W2, const float* W3,
                       const float* g1, const float* v1) {
    int i = blockIdx.x * blockDim.x + threadIdx.x;
    if (i < C_IN * 2 * C_OUT) {
        int k = i / (2 * C_OUT), j = i % (2 * C_OUT);
        float val;
        if (j < C_OUT)
            val = W1[j * (2 * C_IN) + k] - W1[j * (2 * C_IN) + C_IN + k];
        else
            val = W1[(j - C_OUT) * (2 * C_IN) + C_IN + k];
        g_Wct[i] = val;
    }
    if (i < C_OUT * C_OUT) {
        int k = i / C_OUT, n = i % C_OUT;
        float s1 = g1[k] * rsqrtf(v1[k] + BN_EPS);
        g_W2t[i] = W2[n * C_OUT + k] * s1;
        g_W3t[i] = W3[n * C_OUT + k];
    }
}

__global__ void init_agg(int total) {
    int i = blockIdx.x * blockDim.x + threadIdx.x;
    if (i < total) g_agg[i] = -FLT_MAX;
}

// ---- kernel 1: node GEMM -> A|B table ---------------------------------------
__global__ void __launch_bounds__(NTHR, 2)
k1_node_gemm(const float* __restrict__ x, const float* __restrict__ b1, int Nn) {
    extern __shared__ float sh[];
    float2* sV2 = (float2*)sh;
    float*  sW  = sh + TM * SVS * 2;
    int tid = threadIdx.x;
    int mg = tid >> 5, ng = tid & 31;
    int row = tid >> 2, q = tid & 3;
    int m0 = blockIdx.x * TM;
    int jh = blockIdx.y;
    int node = m0 + row; if (node >= Nn) node = Nn - 1;

    unsigned long long acc[8][4];
#pragma unroll
    for (int i = 0; i < 8; ++i)
#pragma unroll
        for (int p = 0; p < 4; ++p) acc[i][p] = 0ull;

    for (int kc = 0; kc < C_IN; kc += KC) {
        load_w_chunk(sW, g_Wct + (size_t)kc * (2 * C_OUT) + jh * C_OUT, 2 * C_OUT, tid);
        const float4* xr = (const float4*)(x + (size_t)node * C_IN + kc) + q * 4;
        float2* d = sV2 + row * SVS + q * 16;
#pragma unroll
        for (int j = 0; j < 4; ++j) {
            float4 v = xr[j];
            d[j * 4 + 0] = make_float2(v.x, v.x);
            d[j * 4 + 1] = make_float2(v.y, v.y);
            d[j * 4 + 2] = make_float2(v.z, v.z);
            d[j * 4 + 3] = make_float2(v.w, v.w);
        }
        __syncthreads();
        gemm_chunk(sV2, sW, acc, mg, ng);
        __syncthreads();
    }

    int n0 = ng * 8;
#pragma unroll
    for (int i = 0; i < 8; ++i) {
        int nd = m0 + mg * 8 + i;
        if (nd >= Nn) break;
        float* dst = g_AB + (size_t)nd * (2 * C_OUT) + jh * C_OUT + n0;
#pragma unroll
        for (int p = 0; p < 4; ++p) {
            float2 z = unpack2(acc[i][p]);
            if (jh == 0) {
                z.x += __ldg(&b1[n0 + 2 * p]);
                z.y += __ldg(&b1[n0 + 2 * p + 1]);
            }
            dst[2 * p]     = z.x;
            dst[2 * p + 1] = z.y;
        }
    }
}

// ---- kernel 2: fused sorted-message GEMM + run-combined segment max ---------
__global__ void __launch_bounds__(NTHR, 1)
k2_edge_gemm(long long EN) {
    extern __shared__ float sh[];
    float2* sV2 = (float2*)sh;                 // PROW128 float2
    float*  sW  = sh + PROW128 * 2;            // KC * 256 floats
    __shared__ int sSrc[TM2], sTgt[TM2];

    int tid = threadIdx.x;
    long long m0 = (long long)blockIdx.x * TM2;
    if (tid < TM2) {
        long long m = m0 + tid;
        int s = 0, t = -1;
        if (m < EN) { s = g_osrc[m]; t = g_otgt[m]; }
        sSrc[tid] = s;  sTgt[tid] = t;
    }
    __syncthreads();

    int lane = tid & 31, warp = tid >> 5;
    int rg   = lane >> 4;                      // row group 0/1
    int c0   = (lane & 15) << 4;               // 16-col base
    int wrow = warp * 16 + rg * 8;             // this lane's first row

    unsigned svBase = (unsigned)__cvta_generic_to_shared(sV2);
    unsigned swBase = (unsigned)__cvta_generic_to_shared(sW);
    unsigned vAddr  = svBase + (unsigned)(prow2(wrow) * 8);
    unsigned wAddr  = swBase + (unsigned)(c0 * 4);

    // staging mapping: 2 threads per row, 32 k's each
    int srow = tid >> 1, soff = (tid & 1) * 32;
    int stgt = sTgt[srow]; if (stgt < 0) stgt = 0;
    int ssrc = sSrc[srow];
    const float* Arow = g_AB + (size_t)stgt * (2 * C_OUT);
    const float* Brow = g_AB + (size_t)ssrc * (2 * C_OUT) + C_OUT;
    float2* dstg = sV2 + prow2(srow) + soff;

    unsigned long long acc[8][8];
#pragma unroll
    for (int i = 0; i < 8; ++i)
#pragma unroll
        for (int p = 0; p < 8; ++p) acc[i][p] = 0ull;

    for (int kc = 0; kc < C_OUT; kc += KC) {
        load_w_chunk(sW, g_W2t + (size_t)kc * C_OUT, C_OUT, tid);
        const float4* ar = (const float4*)(Arow + kc + soff);
        const float4* br = (const float4*)(Brow + kc + soff);
#pragma unroll
        for (int j = 0; j < 8; ++j) {
            float4 a = ar[j], b = br[j];
            float vx = fmaxf(a.x + b.x, 0.0f);
            float vy = fmaxf(a.y + b.y, 0.0f);
            float vz = fmaxf(a.z + b.z, 0.0f);
            float vw = fmaxf(a.w + b.w, 0.0f);
            *(float4*)(dstg + j * 4)     = make_float4(vx, vx, vy, vy);
            *(float4*)(dstg + j * 4 + 2) = make_float4(vz, vz, vw, vw);
        }
        __syncthreads();

#pragma unroll 2
        for (int k = 0; k < KC; k += 2) {
            unsigned long long wa[8], wb[8];
            unsigned wk = wAddr + (unsigned)(k * 1024);
#pragma unroll
            for (int j = 0; j < 4; ++j) lds_v2u64(wa[2 * j], wa[2 * j + 1], wk + j * 16);
#pragma unroll
            for (int j = 0; j < 4; ++j) lds_v2u64(wb[2 * j], wb[2 * j + 1], wk + 1024 + j * 16);
#pragma unroll
            for (int i = 0; i < 8; ++i) {
                unsigned long long va, vb;
                lds_v2u64(va, vb, vAddr + (unsigned)(i * (SVS2 * 8) + k * 8));
#pragma unroll
                for (int p = 0; p < 8; ++p) acc[i][p] = fma2(va, wa[p], acc[i][p]);
#pragma unroll
                for (int p = 0; p < 8; ++p) acc[i][p] = fma2(vb, wb[p], acc[i][p]);
            }
        }
        __syncthreads();
    }

    // ---- epilogue: run-combined max (relu part), BN2 at flush ----------------
    float c2v[16];
#pragma unroll
    for (int j = 0; j < 16; ++j) c2v[j] = __ldg(&g_c2[c0 + j]);

    float rmax[16], rmin[16];
#pragma unroll
    for (int j = 0; j < 16; ++j) { rmax[j] = -FLT_MAX; rmin[j] = FLT_MAX; }

    int cur = sTgt[wrow];
#pragma unroll
    for (int i = 0; i < 8; ++i) {
        int t = sTgt[wrow + i];
        if (t != cur) {
            if (cur >= 0) {
                float* dst = g_agg + (size_t)cur * C_OUT + c0;
#pragma unroll
                for (int j = 0; j < 16; ++j) {
                    float s2 = __ldg(&g_s2[c0 + j]);
                    float t2 = __ldg(&g_t2[c0 + j]);
                    float cand = (s2 >= 0.0f ? rmax[j] : rmin[j]) * s2 + t2;
                    atomicMaxF(dst + j, cand);
                }
            }
#pragma unroll
            for (int j = 0; j < 16; ++j) { rmax[j] = -FLT_MAX; rmin[j] = FLT_MAX; }
            cur = t;
        }
#pragma unroll
        for (int p = 0; p < 8; ++p) {
            float2 z = unpack2(acc[i][p]);
            float u0 = fmaxf(z.x + c2v[2 * p],     0.0f);
            float u1 = fmaxf(z.y + c2v[2 * p + 1], 0.0f);
            rmax[2 * p]     = fmaxf(rmax[2 * p],     u0);
            rmin[2 * p]     = fminf(rmin[2 * p],     u0);
            rmax[2 * p + 1] = fmaxf(rmax[2 * p + 1], u1);
            rmin[2 * p + 1] = fminf(rmin[2 * p + 1], u1);
        }
    }
    if (cur >= 0) {
        float* dst = g_agg + (size_t)cur * C_OUT + c0;
#pragma unroll
        for (int j = 0; j < 16; ++j) {
            float s2 = __ldg(&g_s2[c0 + j]);
            float t2 = __ldg(&g_t2[c0 + j]);
            float cand = (s2 >= 0.0f ? rmax[j] : rmin[j]) * s2 + t2;
            atomicMaxF(dst + j, cand);
        }
    }
}

// ---- kernel 3: out = BN3(relu(agg @ W3^T + b3)) -----------------------------
__global__ void __launch_bounds__(NTHR, 2)
k3_out_gemm(const float* __restrict__ b3, float* __restrict__ out, int Nn) {
    extern __shared__ float sh[];
    float2* sV2 = (float2*)sh;
    float*  sW  = sh + TM * SVS * 2;
    int tid = threadIdx.x;
    int mg = tid >> 5, ng = tid & 31;
    int row = tid >> 2, q = tid & 3;
    int m0 = blockIdx.x * TM;
    int node = m0 + row; if (node >= Nn) node = Nn - 1;

    unsigned long long acc[8][4];
#pragma unroll
    for (int i = 0; i < 8; ++i)
#pragma unroll
        for (int p = 0; p < 4; ++p) acc[i][p] = 0ull;

    const float* Ar = g_agg + (size_t)node * C_OUT;
    for (int kc = 0; kc < C_OUT; kc += KC) {
        load_w_chunk(sW, g_W3t + (size_t)kc * C_OUT, C_OUT, tid);
        const float4* ar = (const float4*)(Ar + kc) + q * 4;
        float2* d = sV2 + row * SVS + q * 16;
#pragma unroll
        for (int j = 0; j < 4; ++j) {
            float4 v = ar[j];
            d[j * 4 + 0] = make_float2(v.x, v.x);
            d[j * 4 + 1] = make_float2(v.y, v.y);
            d[j * 4 + 2] = make_float2(v.z, v.z);
            d[j * 4 + 3] = make_float2(v.w, v.w);
        }
        __syncthreads();
        gemm_chunk(sV2, sW, acc, mg, ng);
        __syncthreads();
    }

    int n0 = ng * 8;
    float b3v[8], s3v[8], t3v[8];
#pragma unroll
    for (int u = 0; u < 8; ++u) {
        b3v[u] = __ldg(&b3[n0 + u]);
        s3v[u] = __ldg(&g_s3[n0 + u]);
        t3v[u] = __ldg(&g_t3[n0 + u]);
    }
#pragma unroll
    for (int i = 0; i < 8; ++i) {
        int nd = m0 + mg * 8 + i;
        if (nd >= Nn) break;
        float* dst = out + (size_t)nd * C_OUT + n0;
#pragma unroll
        for (int p = 0; p < 4; ++p) {
            float2 z = unpack2(acc[i][p]);
            dst[2 * p]     = fmaxf(z.x + b3v[2 * p],     0.0f) * s3v[2 * p]     + t3v[2 * p];
            dst[2 * p + 1] = fmaxf(z.y + b3v[2 * p + 1], 0.0f) * s3v[2 * p + 1] + t3v[2 * p + 1];
        }
    }
}

// ---------------------------------------------------------------------------
extern "C" void kernel_launch(void* const* d_in, const int* in_sizes, int n_in,
                              void* d_out, int out_size) {
    const float* x   = (const float*)d_in[0];
    const void*  idx = (const void*)d_in[1];
    const float* W1 = (const float*)d_in[2];  const float* b1 = (const float*)d_in[3];
    const float* g1 = (const float*)d_in[4];  const float* be1= (const float*)d_in[5];
    const float* m1 = (const float*)d_in[6];  const float* v1 = (const float*)d_in[7];
    const float* W2 = (const float*)d_in[8];  const float* b2 = (const float*)d_in[9];
    const float* g2 = (const float*)d_in[10]; const float* be2= (const float*)d_in[11];
    const float* m2 = (const float*)d_in[12]; const float* v2 = (const float*)d_in[13];
    const float* W3 = (const float*)d_in[14]; const float* b3 = (const float*)d_in[15];
    const float* g3 = (const float*)d_in[16]; const float* be3= (const float*)d_in[17];
    const float* m3 = (const float*)d_in[18]; const float* v3 = (const float*)d_in[19];
    float* out = (float*)d_out;

    int Nn = in_sizes[0] / C_IN;
    long long E2 = (long long)in_sizes[1];
    long long E  = E2 >> 1;
    long long EN = E + Nn;

    size_t shmem13 = (size_t)TM * SVS * sizeof(float2) + (size_t)KC * C_OUT * sizeof(float);
    size_t shmem2  = (size_t)PROW128 * sizeof(float2) + (size_t)KC * C_OUT * sizeof(float);
    cudaFuncSetAttribute(k1_node_gemm, cudaFuncAttributeMaxDynamicSharedMemorySize, (int)shmem13);
    cudaFuncSetAttribute(k2_edge_gemm, cudaFuncAttributeMaxDynamicSharedMemorySize, (int)shmem2);
    cudaFuncSetAttribute(k3_out_gemm,  cudaFuncAttributeMaxDynamicSharedMemorySize, (int)shmem13);

    // decode + counting sort by tgt
    detect_idx<<<1, 32>>>((const int*)idx);
    decode_idx<<<(int)((E2 + 255) / 256), 256>>>(idx, E2, Nn);
    hist_zero<<<(Nn + 255) / 256, 256>>>(Nn);
    hist_tgt<<<(int)((E + 255) / 256), 256>>>(E);
    scan_base<<<1, 256>>>(Nn);
    scatter_edges<<<(int)((E + 255) / 256), 256>>>(E);
    scatter_loops<<<(Nn + 255) / 256, 256>>>(Nn);

    prep_bn<<<1, C_OUT>>>(g1, be1, m1, v1, W2, b2, g2, be2, m2, v2, g3, be3, m3, v3);
    prep_w<<<(C_IN * 2 * C_OUT + 255) / 256, 256>>>(W1, W2, W3, g1, v1);

    int total = Nn * C_OUT;
    init_agg<<<(total + 255) / 256, 256>>>(total);

    dim3 grid1((Nn + TM - 1) / TM, 2);
    k1_node_gemm<<<grid1, NTHR, shmem13>>>(x, b1, Nn);

    int nblk2 = (int)((EN + TM2 - 1) / TM2);
    k2_edge_gemm<<<nblk2, NTHR, shmem2>>>(EN);

    k3_out_gemm<<<(Nn + TM - 1) / TM, NTHR, shmem13>>>(b3, out, Nn);
}

// round 10
// speedup vs baseline: 1.3277x; 1.3277x over previous
#include <cuda_runtime.h>
#include <math.h>
#include <float.h>

// ---------------------------------------------------------------------------
// EdgeConv-style GNN block:
//   layer1 factorized over nodes:  pre1(e) = A[tgt] + B[src]
//       A = x @ (W1a - W1b)^T + b1,   B = x @ W1b^T
//   layer2 fused per-message GEMM:  z = relu(pre1) @ W2'^T + c2  (BN1 folded)
//   epilogue: h2 = BN2(relu(z)) -> atomic float max into agg[tgt]
//   layer3: out = BN3(relu(agg @ W3^T + b3))
//
// Lane->column mapping is conflict-free: lane ng owns cols {ng*4..+3} and
// {128+ng*4..+3}; W loads are contiguous 512B warp sweeps (4 phases, 0 conflicts).
// V is staged as duplicated (v,v) pairs with even row stride so a k-pair is one
// 16B broadcast.
// ---------------------------------------------------------------------------

#define C_IN   128
#define C_OUT  256
#define TM     64     // rows per CTA
#define KC     64     // K chunk
#define NTHR   256
#define SVS    66     // float2 row stride (even -> 16B-aligned k-pairs)
#define BN_EPS 1e-5f
#define MAXN   20000
#define MAXE   640000

// ---- static device scratch -------------------------------------------------
static __device__ __align__(128) float g_AB [(size_t)MAXN * 2 * C_OUT];
static __device__ __align__(128) float g_agg[(size_t)MAXN * C_OUT];
static __device__ __align__(128) float g_Wct[C_IN * 2 * C_OUT];
static __device__ __align__(128) float g_W2t[C_OUT * C_OUT];
static __device__ __align__(128) float g_W3t[C_OUT * C_OUT];
static __device__ __align__(128) float g_c2 [C_OUT];
static __device__ __align__(128) float g_s2 [C_OUT], g_t2[C_OUT];
static __device__ __align__(128) float g_s3 [C_OUT], g_t3[C_OUT];
static __device__ __align__(128) int   g_src[MAXE], g_tgt[MAXE];
static __device__ int g_idx64;

// ---- packed fp32x2 FMA ------------------------------------------------------
__device__ __forceinline__ unsigned long long fma2(unsigned long long a,
                                                   unsigned long long b,
                                                   unsigned long long c) {
    unsigned long long d;
    asm("fma.rn.f32x2 %0, %1, %2, %3;" : "=l"(d) : "l"(a), "l"(b), "l"(c));
    return d;
}
__device__ __forceinline__ float2 unpack2(unsigned long long u) {
    float2 f;
    asm("mov.b64 {%0, %1}, %2;" : "=f"(f.x), "=f"(f.y) : "l"(u));
    return f;
}
__device__ __forceinline__ void lds_v2u64(unsigned long long& a, unsigned long long& b,
                                          unsigned int addr) {
    asm volatile("ld.shared.v2.u64 {%0, %1}, [%2];" : "=l"(a), "=l"(b) : "r"(addr));
}

__device__ __forceinline__ void atomicMaxF(float* a, float v) {
    int bits = __float_as_int(v);
    if (bits >= 0) atomicMax((int*)a, bits);
    else           atomicMin((unsigned int*)a, (unsigned int)bits);
}

// ---- conflict-free GEMM inner loop ------------------------------------------
// acc[i][0..1]: cols ng*4..+3 (pairs), acc[i][2..3]: cols 128+ng*4..+3
__device__ __forceinline__ void gemm_chunk2(unsigned vAddr, unsigned wAddr,
                                            unsigned long long acc[8][4]) {
#pragma unroll 2
    for (int k = 0; k < KC; k += 2) {
        unsigned long long w00a, w00b, w01a, w01b, w10a, w10b, w11a, w11b;
        unsigned wk = wAddr + (unsigned)(k * 1024);
        lds_v2u64(w00a, w00b, wk);             // k,   cols lo
        lds_v2u64(w01a, w01b, wk + 512);       // k,   cols hi
        lds_v2u64(w10a, w10b, wk + 1024);      // k+1, cols lo
        lds_v2u64(w11a, w11b, wk + 1536);      // k+1, cols hi
#pragma unroll
        for (int i = 0; i < 8; ++i) {
            unsigned long long va, vb;         // (v_k,v_k),(v_{k+1},v_{k+1})
            lds_v2u64(va, vb, vAddr + (unsigned)(i * (SVS * 8) + k * 8));
            acc[i][0] = fma2(va, w00a, acc[i][0]);
            acc[i][1] = fma2(va, w00b, acc[i][1]);
            acc[i][2] = fma2(va, w01a, acc[i][2]);
            acc[i][3] = fma2(va, w01b, acc[i][3]);
            acc[i][0] = fma2(vb, w10a, acc[i][0]);
            acc[i][1] = fma2(vb, w10b, acc[i][1]);
            acc[i][2] = fma2(vb, w11a, acc[i][2]);
            acc[i][3] = fma2(vb, w11b, acc[i][3]);
        }
    }
}

__device__ __forceinline__ void load_w_chunk(float* sW, const float* __restrict__ gW,
                                             int rowStride, int tid) {
    for (int t = tid; t < KC * (C_OUT / 4); t += NTHR) {
        int kk = t >> 6;
        int c4 = t & 63;
        *(float4*)(sW + kk * C_OUT + (c4 << 2)) =
            *(const float4*)(gW + (size_t)kk * rowStride + (c4 << 2));
    }
}

// stage 16 duplicated values: thread covers k in [q*16, q*16+16)
__device__ __forceinline__ void stage_dup4(float2* d, float4 v) {
    *(float4*)(d)     = make_float4(v.x, v.x, v.y, v.y);
    *(float4*)(d + 2) = make_float4(v.z, v.z, v.w, v.w);
}

// ---- edge index dtype detection + decode ------------------------------------
__global__ void detect_idx(const int* __restrict__ p) {
    if (threadIdx.x == 0) {
        int is64 = 1;
        for (int i = 0; i < 64; ++i)
            if (p[2 * i + 1] != 0) { is64 = 0; break; }
        g_idx64 = is64;
    }
}

__global__ void decode_idx(const void* __restrict__ idxRaw, long long E2, int Nn) {
    long long i = (long long)blockIdx.x * blockDim.x + threadIdx.x;
    if (i >= E2) return;
    int v;
    if (g_idx64) v = (int)((const long long*)idxRaw)[i];
    else         v = ((const int*)idxRaw)[i];
    if (v < 0) v = 0;
    if (v >= Nn) v = Nn - 1;
    long long E = E2 >> 1;
    if (i < E) g_src[i] = v;
    else       g_tgt[i - E] = v;
}

// ---- prep kernels -----------------------------------------------------------
__global__ void prep_bn(const float* g1, const float* be1, const float* m1, const float* v1,
                        const float* W2, const float* b2,
                        const float* g2, const float* be2, const float* m2, const float* v2,
                        const float* g3, const float* be3, const float* m3, const float* v3) {
    int c = threadIdx.x;
    float s2 = g2[c] * rsqrtf(v2[c] + BN_EPS);
    g_s2[c] = s2;  g_t2[c] = be2[c] - m2[c] * s2;
    float s3 = g3[c] * rsqrtf(v3[c] + BN_EPS);
    g_s3[c] = s3;  g_t3[c] = be3[c] - m3[c] * s3;
    float acc = b2[c];
    for (int k = 0; k < C_OUT; ++k) {
        float s1 = g1[k] * rsqrtf(v1[k] + BN_EPS);
        float t1 = be1[k] - m1[k] * s1;
        acc += W2[c * C_OUT + k] * t1;
    }
    g_c2[c] = acc;
}

__global__ void prep_w(const float* W1, const float* W2, const float* W3,
                       const float* g1, const float* v1) {
    int i = blockIdx.x * blockDim.x + threadIdx.x;
    if (i < C_IN * 2 * C_OUT) {
        int k = i / (2 * C_OUT), j = i % (2 * C_OUT);
        float val;
        if (j < C_OUT)
            val = W1[j * (2 * C_IN) + k] - W1[j * (2 * C_IN) + C_IN + k];
        else
            val = W1[(j - C_OUT) * (2 * C_IN) + C_IN + k];
        g_Wct[i] = val;
    }
    if (i < C_OUT * C_OUT) {
        int k = i / C_OUT, n = i % C_OUT;
        float s1 = g1[k] * rsqrtf(v1[k] + BN_EPS);
        g_W2t[i] = W2[n * C_OUT + k] * s1;
        g_W3t[i] = W3[n * C_OUT + k];
    }
}

__global__ void init_agg(int total) {
    int i = blockIdx.x * blockDim.x + threadIdx.x;
    if (i < total) g_agg[i] = -FLT_MAX;
}

// ---- kernel 1: node GEMM -> A|B table ---------------------------------------
__global__ void __launch_bounds__(NTHR, 2)
k1_node_gemm(const float* __restrict__ x, const float* __restrict__ b1, int Nn) {
    extern __shared__ float sh[];
    float2* sV2 = (float2*)sh;
    float*  sW  = sh + TM * SVS * 2;
    int tid = threadIdx.x;
    int warp = tid >> 5, ng = tid & 31;
    int row = tid >> 2, q = tid & 3;
    int m0 = blockIdx.x * TM;
    int jh = blockIdx.y;                       // 0: A half, 1: B half
    int node = m0 + row; if (node >= Nn) node = Nn - 1;

    unsigned svBase = (unsigned)__cvta_generic_to_shared(sV2);
    unsigned swBase = (unsigned)__cvta_generic_to_shared(sW);
    unsigned vAddr  = svBase + (unsigned)(warp * 8 * SVS * 8);
    unsigned wAddr  = swBase + (unsigned)(ng * 16);

    unsigned long long acc[8][4];
#pragma unroll
    for (int i = 0; i < 8; ++i)
#pragma unroll
        for (int p = 0; p < 4; ++p) acc[i][p] = 0ull;

    for (int kc = 0; kc < C_IN; kc += KC) {
        load_w_chunk(sW, g_Wct + (size_t)kc * (2 * C_OUT) + jh * C_OUT, 2 * C_OUT, tid);
        const float4* xr = (const float4*)(x + (size_t)node * C_IN + kc) + q * 4;
        float2* d = sV2 + row * SVS + q * 16;
#pragma unroll
        for (int j = 0; j < 4; ++j) stage_dup4(d + j * 4, xr[j]);
        __syncthreads();
        gemm_chunk2(vAddr, wAddr, acc);
        __syncthreads();
    }

    int cLo = ng * 4, cHi = 128 + ng * 4;
#pragma unroll
    for (int i = 0; i < 8; ++i) {
        int nd = m0 + warp * 8 + i;
        if (nd >= Nn) break;
        float* dst = g_AB + (size_t)nd * (2 * C_OUT) + jh * C_OUT;
#pragma unroll
        for (int p = 0; p < 4; ++p) {
            int c = (p < 2) ? (cLo + 2 * p) : (cHi + 2 * (p - 2));
            float2 z = unpack2(acc[i][p]);
            if (jh == 0) { z.x += __ldg(&b1[c]); z.y += __ldg(&b1[c + 1]); }
            *(float2*)(dst + c) = z;
        }
    }
}

// ---- kernel 2: fused message GEMM + BN2/ReLU + atomic segment max ----------
__global__ void __launch_bounds__(NTHR, 2)
k2_edge_gemm(long long E, int Nn) {
    extern __shared__ float sh[];
    float2* sV2 = (float2*)sh;
    float*  sW  = sh + TM * SVS * 2;
    __shared__ int sTgt[TM];

    int tid = threadIdx.x;
    int warp = tid >> 5, ng = tid & 31;
    int row = tid >> 2, q = tid & 3;
    long long EN = E + (long long)Nn;
    long long m0 = (long long)blockIdx.x * TM;

    if (tid < TM) {
        long long m = m0 + tid;
        int t = 0;
        if (m < E)       t = g_tgt[m];
        else if (m < EN) t = (int)(m - E);
        sTgt[tid] = t;
    }

    // per-thread staging source rows
    long long mrow = m0 + row;
    int s = 0, t = 0;
    if (mrow < E)       { s = g_src[mrow]; t = g_tgt[mrow]; }
    else if (mrow < EN) { s = t = (int)(mrow - E); }
    const float* Arow = g_AB + (size_t)t * (2 * C_OUT);
    const float* Brow = g_AB + (size_t)s * (2 * C_OUT) + C_OUT;

    unsigned svBase = (unsigned)__cvta_generic_to_shared(sV2);
    unsigned swBase = (unsigned)__cvta_generic_to_shared(sW);
    unsigned vAddr  = svBase + (unsigned)(warp * 8 * SVS * 8);
    unsigned wAddr  = swBase + (unsigned)(ng * 16);

    unsigned long long acc[8][4];
#pragma unroll
    for (int i = 0; i < 8; ++i)
#pragma unroll
        for (int p = 0; p < 4; ++p) acc[i][p] = 0ull;

    for (int kc = 0; kc < C_OUT; kc += KC) {
        load_w_chunk(sW, g_W2t + (size_t)kc * C_OUT, C_OUT, tid);
        const float4* ar = (const float4*)(Arow + kc) + q * 4;
        const float4* br = (const float4*)(Brow + kc) + q * 4;
        float2* d = sV2 + row * SVS + q * 16;
#pragma unroll
        for (int j = 0; j < 4; ++j) {
            float4 a = ar[j], b = br[j];
            float4 v = make_float4(fmaxf(a.x + b.x, 0.0f), fmaxf(a.y + b.y, 0.0f),
                                   fmaxf(a.z + b.z, 0.0f), fmaxf(a.w + b.w, 0.0f));
            stage_dup4(d + j * 4, v);
        }
        __syncthreads();
        gemm_chunk2(vAddr, wAddr, acc);
        __syncthreads();
    }

    int cLo = ng * 4, cHi = 128 + ng * 4;
    float c2v[8], s2v[8], t2v[8];
#pragma unroll
    for (int p = 0; p < 4; ++p) {
        int c = (p < 2) ? (cLo + 2 * p) : (cHi + 2 * (p - 2));
        c2v[2 * p] = __ldg(&g_c2[c]);     c2v[2 * p + 1] = __ldg(&g_c2[c + 1]);
        s2v[2 * p] = __ldg(&g_s2[c]);     s2v[2 * p + 1] = __ldg(&g_s2[c + 1]);
        t2v[2 * p] = __ldg(&g_t2[c]);     t2v[2 * p + 1] = __ldg(&g_t2[c + 1]);
    }
#pragma unroll
    for (int i = 0; i < 8; ++i) {
        long long m = m0 + warp * 8 + i;
        if (m >= EN) break;
        float* dst = g_agg + (size_t)sTgt[warp * 8 + i] * C_OUT;
#pragma unroll
        for (int p = 0; p < 4; ++p) {
            int c = (p < 2) ? (cLo + 2 * p) : (cHi + 2 * (p - 2));
            float2 z = unpack2(acc[i][p]);
            float h0 = fmaxf(z.x + c2v[2 * p],     0.0f) * s2v[2 * p]     + t2v[2 * p];
            float h1 = fmaxf(z.y + c2v[2 * p + 1], 0.0f) * s2v[2 * p + 1] + t2v[2 * p + 1];
            atomicMaxF(dst + c,     h0);
            atomicMaxF(dst + c + 1, h1);
        }
    }
}

// ---- kernel 3: out = BN3(relu(agg @ W3^T + b3)) -----------------------------
__global__ void __launch_bounds__(NTHR, 2)
k3_out_gemm(const float* __restrict__ b3, float* __restrict__ out, int Nn) {
    extern __shared__ float sh[];
    float2* sV2 = (float2*)sh;
    float*  sW  = sh + TM * SVS * 2;
    int tid = threadIdx.x;
    int warp = tid >> 5, ng = tid & 31;
    int row = tid >> 2, q = tid & 3;
    int m0 = blockIdx.x * TM;
    int node = m0 + row; if (node >= Nn) node = Nn - 1;

    unsigned svBase = (unsigned)__cvta_generic_to_shared(sV2);
    unsigned swBase = (unsigned)__cvta_generic_to_shared(sW);
    unsigned vAddr  = svBase + (unsigned)(warp * 8 * SVS * 8);
    unsigned wAddr  = swBase + (unsigned)(ng * 16);

    unsigned long long acc[8][4];
#pragma unroll
    for (int i = 0; i < 8; ++i)
#pragma unroll
        for (int p = 0; p < 4; ++p) acc[i][p] = 0ull;

    const float* Ar = g_agg + (size_t)node * C_OUT;
    for (int kc = 0; kc < C_OUT; kc += KC) {
        load_w_chunk(sW, g_W3t + (size_t)kc * C_OUT, C_OUT, tid);
        const float4* ar = (const float4*)(Ar + kc) + q * 4;
        float2* d = sV2 + row * SVS + q * 16;
#pragma unroll
        for (int j = 0; j < 4; ++j) stage_dup4(d + j * 4, ar[j]);
        __syncthreads();
        gemm_chunk2(vAddr, wAddr, acc);
        __syncthreads();
    }

    int cLo = ng * 4, cHi = 128 + ng * 4;
#pragma unroll
    for (int i = 0; i < 8; ++i) {
        int nd = m0 + warp * 8 + i;
        if (nd >= Nn) break;
        float* dst = out + (size_t)nd * C_OUT;
#pragma unroll
        for (int p = 0; p < 4; ++p) {
            int c = (p < 2) ? (cLo + 2 * p) : (cHi + 2 * (p - 2));
            float2 z = unpack2(acc[i][p]);
            float o0 = fmaxf(z.x + __ldg(&b3[c]),     0.0f) * __ldg(&g_s3[c])     + __ldg(&g_t3[c]);
            float o1 = fmaxf(z.y + __ldg(&b3[c + 1]), 0.0f) * __ldg(&g_s3[c + 1]) + __ldg(&g_t3[c + 1]);
            *(float2*)(dst + c) = make_float2(o0, o1);
        }
    }
}

// ---------------------------------------------------------------------------
extern "C" void kernel_launch(void* const* d_in, const int* in_sizes, int n_in,
                              void* d_out, int out_size) {
    const float* x   = (const float*)d_in[0];
    const void*  idx = (const void*)d_in[1];
    const float* W1 = (const float*)d_in[2];  const float* b1 = (const float*)d_in[3];
    const float* g1 = (const float*)d_in[4];  const float* be1= (const float*)d_in[5];
    const float* m1 = (const float*)d_in[6];  const float* v1 = (const float*)d_in[7];
    const float* W2 = (const float*)d_in[8];  const float* b2 = (const float*)d_in[9];
    const float* g2 = (const float*)d_in[10]; const float* be2= (const float*)d_in[11];
    const float* m2 = (const float*)d_in[12]; const float* v2 = (const float*)d_in[13];
    const float* W3 = (const float*)d_in[14]; const float* b3 = (const float*)d_in[15];
    const float* g3 = (const float*)d_in[16]; const float* be3= (const float*)d_in[17];
    const float* m3 = (const float*)d_in[18]; const float* v3 = (const float*)d_in[19];
    float* out = (float*)d_out;

    int Nn = in_sizes[0] / C_IN;
    long long E2 = (long long)in_sizes[1];
    long long E  = E2 >> 1;
    long long EN = E + Nn;

    size_t shmem = (size_t)TM * SVS * sizeof(float2) + (size_t)KC * C_OUT * sizeof(float);
    cudaFuncSetAttribute(k1_node_gemm, cudaFuncAttributeMaxDynamicSharedMemorySize, (int)shmem);
    cudaFuncSetAttribute(k2_edge_gemm, cudaFuncAttributeMaxDynamicSharedMemorySize, (int)shmem);
    cudaFuncSetAttribute(k3_out_gemm,  cudaFuncAttributeMaxDynamicSharedMemorySize, (int)shmem);

    detect_idx<<<1, 32>>>((const int*)idx);
    decode_idx<<<(int)((E2 + 255) / 256), 256>>>(idx, E2, Nn);

    prep_bn<<<1, C_OUT>>>(g1, be1, m1, v1, W2, b2, g2, be2, m2, v2, g3, be3, m3, v3);
    prep_w<<<(C_IN * 2 * C_OUT + 255) / 256, 256>>>(W1, W2, W3, g1, v1);

    int total = Nn * C_OUT;
    init_agg<<<(total + 255) / 256, 256>>>(total);

    dim3 grid1((Nn + TM - 1) / TM, 2);
    k1_node_gemm<<<grid1, NTHR, shmem>>>(x, b1, Nn);

    int nblk2 = (int)((EN + TM - 1) / TM);
    k2_edge_gemm<<<nblk2, NTHR, shmem>>>(E, Nn);

    k3_out_gemm<<<(Nn + TM - 1) / TM, NTHR, shmem>>>(b3, out, Nn);
}

// round 12
// speedup vs baseline: 2.1855x; 1.6461x over previous
#include <cuda_runtime.h>
#include <cuda_bf16.h>
#include <math.h>
#include <float.h>
#include <stdint.h>

// ---------------------------------------------------------------------------
// EdgeConv GNN block (plain sm_103-safe: no tcgen05, tensor via mma.sync bf16)
//  k1 (fp32 FFMA2): A = x(W1a-W1b)^T + b1, B = x W1b^T  -> g_AB
//  k2 (mma.sync bf16, 3-pass hi/lo): per 64-message tile,
//      V = relu(A[tgt]+B[src]) split hi/lo bf16; W2' (BN1-folded) pre-split;
//      C(fp32) += Vh*Wh + Vh*Wl + Vl*Wh over K=256 (4 chunks of 64);
//      epilogue: BN2(relu(C + c2)) -> atomic float max into g_agg[tgt]
//  k3 (fp32 FFMA2): out = BN3(relu(agg W3^T + b3))
// ---------------------------------------------------------------------------

#define C_IN   128
#define C_OUT  256
#define TM     64
#define KC     64
#define NTHR   256
#define SVS    66
#define BN_EPS 1e-5f
#define MAXN   20000
#define MAXE   640000

// ---- static device scratch -------------------------------------------------
static __device__ __align__(128) float g_AB [(size_t)MAXN * 2 * C_OUT];
static __device__ __align__(128) float g_agg[(size_t)MAXN * C_OUT];
static __device__ __align__(128) float g_Wct[C_IN * 2 * C_OUT];
static __device__ __align__(128) float g_W3t[C_OUT * C_OUT];
static __device__ __align__(128) __nv_bfloat16 g_W2h[C_OUT * C_OUT]; // [n][k] hi
static __device__ __align__(128) __nv_bfloat16 g_W2l[C_OUT * C_OUT]; // [n][k] lo
static __device__ __align__(128) float g_c2 [C_OUT];
static __device__ __align__(128) float g_s2 [C_OUT], g_t2[C_OUT];
static __device__ __align__(128) float g_s3 [C_OUT], g_t3[C_OUT];
static __device__ __align__(128) int   g_src[MAXE], g_tgt[MAXE];
static __device__ int g_idx64;

// ---- PTX helpers ------------------------------------------------------------
__device__ __forceinline__ unsigned long long fma2(unsigned long long a,
                                                   unsigned long long b,
                                                   unsigned long long c) {
    unsigned long long d;
    asm("fma.rn.f32x2 %0, %1, %2, %3;" : "=l"(d) : "l"(a), "l"(b), "l"(c));
    return d;
}
__device__ __forceinline__ float2 unpack2(unsigned long long u) {
    float2 f;
    asm("mov.b64 {%0, %1}, %2;" : "=f"(f.x), "=f"(f.y) : "l"(u));
    return f;
}
__device__ __forceinline__ void lds_v2u64(unsigned long long& a, unsigned long long& b,
                                          unsigned int addr) {
    asm volatile("ld.shared.v2.u64 {%0, %1}, [%2];" : "=l"(a), "=l"(b) : "r"(addr));
}
__device__ __forceinline__ void atomicMaxF(float* a, float v) {
    int bits = __float_as_int(v);
    if (bits >= 0) atomicMax((int*)a, bits);
    else           atomicMin((unsigned int*)a, (unsigned int)bits);
}
__device__ __forceinline__ uint32_t smem_u32(const void* p) {
    uint32_t a;
    asm("{ .reg .u64 t; cvta.to.shared.u64 t, %1; cvt.u32.u64 %0, t; }"
        : "=r"(a) : "l"(p));
    return a;
}
__device__ __forceinline__ uint32_t pack_bf2(float a, float b) {
    __nv_bfloat162 p = __floats2bfloat162_rn(a, b);
    return *(uint32_t*)&p;
}

#define SWZ(o) ((o) ^ (((o) >> 3) & 0x70))

#define LDSM4(r0, r1, r2, r3, addr) \
    asm volatile("ldmatrix.sync.aligned.m8n8.x4.shared.b16 {%0,%1,%2,%3}, [%4];" \
                 : "=r"(r0), "=r"(r1), "=r"(r2), "=r"(r3) : "r"(addr))

#define MMA_BF16(d, a, b0, b1) \
    asm volatile("mma.sync.aligned.m16n8k16.row.col.f32.bf16.bf16.f32 " \
                 "{%0,%1,%2,%3}, {%4,%5,%6,%7}, {%8,%9}, {%0,%1,%2,%3};" \
                 : "+f"((d)[0]), "+f"((d)[1]), "+f"((d)[2]), "+f"((d)[3]) \
                 : "r"((a)[0]), "r"((a)[1]), "r"((a)[2]), "r"((a)[3]), \
                   "r"(b0), "r"(b1))

// ---- fp32 FFMA2 GEMM inner loop (k1/k3, proven R10 version) -----------------
__device__ __forceinline__ void gemm_chunk2(unsigned vAddr, unsigned wAddr,
                                            unsigned long long acc[8][4]) {
#pragma unroll 2
    for (int k = 0; k < KC; k += 2) {
        unsigned long long w00a, w00b, w01a, w01b, w10a, w10b, w11a, w11b;
        unsigned wk = wAddr + (unsigned)(k * 1024);
        lds_v2u64(w00a, w00b, wk);
        lds_v2u64(w01a, w01b, wk + 512);
        lds_v2u64(w10a, w10b, wk + 1024);
        lds_v2u64(w11a, w11b, wk + 1536);
#pragma unroll
        for (int i = 0; i < 8; ++i) {
            unsigned long long va, vb;
            lds_v2u64(va, vb, vAddr + (unsigned)(i * (SVS * 8) + k * 8));
            acc[i][0] = fma2(va, w00a, acc[i][0]);
            acc[i][1] = fma2(va, w00b, acc[i][1]);
            acc[i][2] = fma2(va, w01a, acc[i][2]);
            acc[i][3] = fma2(va, w01b, acc[i][3]);
            acc[i][0] = fma2(vb, w10a, acc[i][0]);
            acc[i][1] = fma2(vb, w10b, acc[i][1]);
            acc[i][2] = fma2(vb, w11a, acc[i][2]);
            acc[i][3] = fma2(vb, w11b, acc[i][3]);
        }
    }
}

__device__ __forceinline__ void load_w_chunk(float* sW, const float* __restrict__ gW,
                                             int rowStride, int tid) {
    for (int t = tid; t < KC * (C_OUT / 4); t += NTHR) {
        int kk = t >> 6;
        int c4 = t & 63;
        *(float4*)(sW + kk * C_OUT + (c4 << 2)) =
            *(const float4*)(gW + (size_t)kk * rowStride + (c4 << 2));
    }
}
__device__ __forceinline__ void stage_dup4(float2* d, float4 v) {
    *(float4*)(d)     = make_float4(v.x, v.x, v.y, v.y);
    *(float4*)(d + 2) = make_float4(v.z, v.z, v.w, v.w);
}

// ---- edge index dtype detection + decode ------------------------------------
__global__ void detect_idx(const int* __restrict__ p) {
    if (threadIdx.x == 0) {
        int is64 = 1;
        for (int i = 0; i < 64; ++i)
            if (p[2 * i + 1] != 0) { is64 = 0; break; }
        g_idx64 = is64;
    }
}
__global__ void decode_idx(const void* __restrict__ idxRaw, long long E2, int Nn) {
    long long i = (long long)blockIdx.x * blockDim.x + threadIdx.x;
    if (i >= E2) return;
    int v;
    if (g_idx64) v = (int)((const long long*)idxRaw)[i];
    else         v = ((const int*)idxRaw)[i];
    if (v < 0) v = 0;
    if (v >= Nn) v = Nn - 1;
    long long E = E2 >> 1;
    if (i < E) g_src[i] = v;
    else       g_tgt[i - E] = v;
}

// ---- prep kernels -----------------------------------------------------------
__global__ void prep_bn(const float* g1, const float* be1, const float* m1, const float* v1,
                        const float* W2, const float* b2,
                        const float* g2, const float* be2, const float* m2, const float* v2,
                        const float* g3, const float* be3, const float* m3, const float* v3) {
    int c = threadIdx.x;
    float s2 = g2[c] * rsqrtf(v2[c] + BN_EPS);
    g_s2[c] = s2;  g_t2[c] = be2[c] - m2[c] * s2;
    float s3 = g3[c] * rsqrtf(v3[c] + BN_EPS);
    g_s3[c] = s3;  g_t3[c] = be3[c] - m3[c] * s3;
    float acc = b2[c];
    for (int k = 0; k < C_OUT; ++k) {
        float s1 = g1[k] * rsqrtf(v1[k] + BN_EPS);
        float t1 = be1[k] - m1[k] * s1;
        acc += W2[c * C_OUT + k] * t1;
    }
    g_c2[c] = acc;
}

__global__ void prep_w(const float* W1, const float* W2, const float* W3,
                       const float* g1, const float* v1) {
    int i = blockIdx.x * blockDim.x + threadIdx.x;
    if (i < C_IN * 2 * C_OUT) {
        int k = i / (2 * C_OUT), j = i % (2 * C_OUT);
        float val;
        if (j < C_OUT)
            val = W1[j * (2 * C_IN) + k] - W1[j * (2 * C_IN) + C_IN + k];
        else
            val = W1[(j - C_OUT) * (2 * C_IN) + C_IN + k];
        g_Wct[i] = val;
    }
    if (i < C_OUT * C_OUT) {
        int k = i / C_OUT, n = i % C_OUT;
        float s1 = g1[k] * rsqrtf(v1[k] + BN_EPS);
        g_W3t[i] = W3[n * C_OUT + k];                   // [k][n] for k3
        // W2 hi/lo split, [n][k] k-contiguous layout (B^T row-major = B col-major)
        int nn = i / C_OUT, kk = i % C_OUT;
        float s1k = g1[kk] * rsqrtf(v1[kk] + BN_EPS);
        float w = W2[nn * C_OUT + kk] * s1k;
        __nv_bfloat16 hb = __float2bfloat16(w);
        g_W2h[i] = hb;
        g_W2l[i] = __float2bfloat16(w - __bfloat162float(hb));
    }
}

__global__ void init_agg(int total) {
    int i = blockIdx.x * blockDim.x + threadIdx.x;
    if (i < total) g_agg[i] = -FLT_MAX;
}

// ---- kernel 1: node GEMM -> A|B table (fp32 FFMA2) --------------------------
__global__ void __launch_bounds__(NTHR, 2)
k1_node_gemm(const float* __restrict__ x, const float* __restrict__ b1, int Nn) {
    extern __shared__ float sh[];
    float2* sV2 = (float2*)sh;
    float*  sW  = sh + TM * SVS * 2;
    int tid = threadIdx.x;
    int warp = tid >> 5, ng = tid & 31;
    int row = tid >> 2, q = tid & 3;
    int m0 = blockIdx.x * TM;
    int jh = blockIdx.y;
    int node = m0 + row; if (node >= Nn) node = Nn - 1;

    unsigned vAddr = smem_u32(sV2) + (unsigned)(warp * 8 * SVS * 8);
    unsigned wAddr = smem_u32(sW) + (unsigned)(ng * 16);

    unsigned long long acc[8][4];
#pragma unroll
    for (int i = 0; i < 8; ++i)
#pragma unroll
        for (int p = 0; p < 4; ++p) acc[i][p] = 0ull;

    for (int kc = 0; kc < C_IN; kc += KC) {
        load_w_chunk(sW, g_Wct + (size_t)kc * (2 * C_OUT) + jh * C_OUT, 2 * C_OUT, tid);
        const float4* xr = (const float4*)(x + (size_t)node * C_IN + kc) + q * 4;
        float2* d = sV2 + row * SVS + q * 16;
#pragma unroll
        for (int j = 0; j < 4; ++j) stage_dup4(d + j * 4, xr[j]);
        __syncthreads();
        gemm_chunk2(vAddr, wAddr, acc);
        __syncthreads();
    }

    int cLo = ng * 4, cHi = 128 + ng * 4;
#pragma unroll
    for (int i = 0; i < 8; ++i) {
        int nd = m0 + warp * 8 + i;
        if (nd >= Nn) break;
        float* dst = g_AB + (size_t)nd * (2 * C_OUT) + jh * C_OUT;
#pragma unroll
        for (int p = 0; p < 4; ++p) {
            int c = (p < 2) ? (cLo + 2 * p) : (cHi + 2 * (p - 2));
            float2 z = unpack2(acc[i][p]);
            if (jh == 0) { z.x += __ldg(&b1[c]); z.y += __ldg(&b1[c + 1]); }
            *(float2*)(dst + c) = z;
        }
    }
}

// ---- kernel 2: mma.sync bf16 3-pass message GEMM ----------------------------
// smem byte offsets (base assumed >= 1KB aligned; swizzle is base-relative)
#define SM_TGT   0                    // 64 ints
#define SM_VHI   1024                 // 64 rows x 128B
#define SM_VLO   (SM_VHI + 8192)
#define SM_WHI   (SM_VLO + 8192)      // 256 rows x 128B
#define SM_WLO   (SM_WHI + 32768)
#define SM_TOT   (SM_WLO + 32768)     // 82944 bytes

__global__ void __launch_bounds__(NTHR, 2)
k2_edge_mma(long long E, int Nn) {
    extern __shared__ char smem[];
    uint32_t sb = smem_u32(smem);
    int tid = threadIdx.x;
    int lane = tid & 31, w = tid >> 5;
    int rg = w & 3, cg = w >> 2;                 // 4 row groups x 2 col halves
    long long EN = E + (long long)Nn;
    long long m0 = (long long)blockIdx.x * 64;

    int* sTgt = (int*)(smem + SM_TGT);
    if (tid < 64) {
        long long m = m0 + tid;
        int t = -1;
        if (m < E)       t = g_tgt[m];
        else if (m < EN) t = (int)(m - E);
        sTgt[tid] = t;
    }

    // staging source: thread covers row r, k-quarter q (16 floats per chunk)
    int r = tid >> 2, q = tid & 3;
    long long mr = m0 + r;
    int s = 0, t = 0;
    if (mr < E)       { s = g_src[mr]; t = g_tgt[mr]; }
    else if (mr < EN) { s = t = (int)(mr - E); }
    const float* Arow = g_AB + (size_t)t * (2 * C_OUT);
    const float* Brow = g_AB + (size_t)s * (2 * C_OUT) + C_OUT;

    float c[16][4];
#pragma unroll
    for (int i = 0; i < 16; ++i)
#pragma unroll
        for (int p = 0; p < 4; ++p) c[i][p] = 0.0f;

    for (int kc = 0; kc < C_OUT; kc += 64) {
        // ---- stage V hi/lo: relu(A+B), bf16 split, SW128 swizzled ----------
        {
            const float4* a4 = (const float4*)(Arow + kc) + q * 4;
            const float4* b4 = (const float4*)(Brow + kc) + q * 4;
            uint32_t H[8], L[8];
#pragma unroll
            for (int j = 0; j < 4; ++j) {
                float4 a = a4[j], b = b4[j];
                float u0 = fmaxf(a.x + b.x, 0.0f);
                float u1 = fmaxf(a.y + b.y, 0.0f);
                float u2 = fmaxf(a.z + b.z, 0.0f);
                float u3 = fmaxf(a.w + b.w, 0.0f);
                __nv_bfloat16 h0 = __float2bfloat16(u0), h1 = __float2bfloat16(u1);
                __nv_bfloat16 h2 = __float2bfloat16(u2), h3 = __float2bfloat16(u3);
                H[j * 2 + 0] = pack_bf2(__bfloat162float(h0), __bfloat162float(h1));
                H[j * 2 + 1] = pack_bf2(__bfloat162float(h2), __bfloat162float(h3));
                L[j * 2 + 0] = pack_bf2(u0 - __bfloat162float(h0), u1 - __bfloat162float(h1));
                L[j * 2 + 1] = pack_bf2(u2 - __bfloat162float(h2), u3 - __bfloat162float(h3));
            }
            uint32_t off = (uint32_t)(r * 128 + q * 32);
            *(uint4*)(smem + SM_VHI + SWZ(off))      = make_uint4(H[0], H[1], H[2], H[3]);
            *(uint4*)(smem + SM_VHI + SWZ(off + 16)) = make_uint4(H[4], H[5], H[6], H[7]);
            *(uint4*)(smem + SM_VLO + SWZ(off))      = make_uint4(L[0], L[1], L[2], L[3]);
            *(uint4*)(smem + SM_VLO + SWZ(off + 16)) = make_uint4(L[4], L[5], L[6], L[7]);
        }
        // ---- stage W hi/lo: row n = tid, 128B per chunk --------------------
        {
            const uint4* gh = (const uint4*)((const char*)g_W2h + (size_t)tid * 512 + kc * 2);
            const uint4* gl = (const uint4*)((const char*)g_W2l + (size_t)tid * 512 + kc * 2);
#pragma unroll
            for (int j = 0; j < 8; ++j) {
                uint32_t off = (uint32_t)(tid * 128 + j * 16);
                uint32_t swo = SWZ(off);
                *(uint4*)(smem + SM_WHI + swo) = gh[j];
                *(uint4*)(smem + SM_WLO + swo) = gl[j];
            }
        }
        __syncthreads();

        // ---- compute: 4 k16 steps, 3 passes ---------------------------------
#pragma unroll
        for (int ks = 0; ks < 4; ++ks) {
            uint32_t aoff = SWZ((uint32_t)((rg * 16 + (lane & 15)) * 128 +
                                           ks * 32 + (lane >> 4) * 16));
            uint32_t ah[4], al[4];
            LDSM4(ah[0], ah[1], ah[2], ah[3], sb + SM_VHI + aoff);
            LDSM4(al[0], al[1], al[2], al[3], sb + SM_VLO + aoff);
#pragma unroll
            for (int jj = 0; jj < 8; ++jj) {
                uint32_t boff = SWZ((uint32_t)((cg * 128 + jj * 16 + (lane & 15)) * 128 +
                                               ks * 32 + (lane >> 4) * 16));
                uint32_t bh[4], bl[4];
                LDSM4(bh[0], bh[1], bh[2], bh[3], sb + SM_WHI + boff);
                LDSM4(bl[0], bl[1], bl[2], bl[3], sb + SM_WLO + boff);
                MMA_BF16(c[2 * jj],     ah, bh[0], bh[2]);
                MMA_BF16(c[2 * jj + 1], ah, bh[1], bh[3]);
                MMA_BF16(c[2 * jj],     ah, bl[0], bl[2]);
                MMA_BF16(c[2 * jj + 1], ah, bl[1], bl[3]);
                MMA_BF16(c[2 * jj],     al, bh[0], bh[2]);
                MMA_BF16(c[2 * jj + 1], al, bh[1], bh[3]);
            }
        }
        __syncthreads();
    }

    // ---- epilogue: BN2(relu(z + c2)) -> atomic max into g_agg[tgt] ---------
    int r0 = rg * 16 + (lane >> 2), r1 = r0 + 8;
    int t0 = sTgt[r0], t1 = sTgt[r1];
    float* dst0 = g_agg + (size_t)(t0 < 0 ? 0 : t0) * C_OUT;
    float* dst1 = g_agg + (size_t)(t1 < 0 ? 0 : t1) * C_OUT;
#pragma unroll
    for (int jj = 0; jj < 16; ++jj) {
        int cn = cg * 128 + jj * 8 + (lane & 3) * 2;
        float c2a = __ldg(&g_c2[cn]),     c2b = __ldg(&g_c2[cn + 1]);
        float s2a = __ldg(&g_s2[cn]),     s2b = __ldg(&g_s2[cn + 1]);
        float t2a = __ldg(&g_t2[cn]),     t2b = __ldg(&g_t2[cn + 1]);
        if (t0 >= 0) {
            atomicMaxF(dst0 + cn,     fmaxf(c[jj][0] + c2a, 0.0f) * s2a + t2a);
            atomicMaxF(dst0 + cn + 1, fmaxf(c[jj][1] + c2b, 0.0f) * s2b + t2b);
        }
        if (t1 >= 0) {
            atomicMaxF(dst1 + cn,     fmaxf(c[jj][2] + c2a, 0.0f) * s2a + t2a);
            atomicMaxF(dst1 + cn + 1, fmaxf(c[jj][3] + c2b, 0.0f) * s2b + t2b);
        }
    }
}

// ---- kernel 3: out = BN3(relu(agg @ W3^T + b3)) (fp32 FFMA2) ----------------
__global__ void __launch_bounds__(NTHR, 2)
k3_out_gemm(const float* __restrict__ b3, float* __restrict__ out, int Nn) {
    extern __shared__ float sh[];
    float2* sV2 = (float2*)sh;
    float*  sW  = sh + TM * SVS * 2;
    int tid = threadIdx.x;
    int warp = tid >> 5, ng = tid & 31;
    int row = tid >> 2, q = tid & 3;
    int m0 = blockIdx.x * TM;
    int node = m0 + row; if (node >= Nn) node = Nn - 1;

    unsigned vAddr = smem_u32(sV2) + (unsigned)(warp * 8 * SVS * 8);
    unsigned wAddr = smem_u32(sW) + (unsigned)(ng * 16);

    unsigned long long acc[8][4];
#pragma unroll
    for (int i = 0; i < 8; ++i)
#pragma unroll
        for (int p = 0; p < 4; ++p) acc[i][p] = 0ull;

    const float* Ar = g_agg + (size_t)node * C_OUT;
    for (int kc = 0; kc < C_OUT; kc += KC) {
        load_w_chunk(sW, g_W3t + (size_t)kc * C_OUT, C_OUT, tid);
        const float4* ar = (const float4*)(Ar + kc) + q * 4;
        float2* d = sV2 + row * SVS + q * 16;
#pragma unroll
        for (int j = 0; j < 4; ++j) stage_dup4(d + j * 4, ar[j]);
        __syncthreads();
        gemm_chunk2(vAddr, wAddr, acc);
        __syncthreads();
    }

    int cLo = ng * 4, cHi = 128 + ng * 4;
#pragma unroll
    for (int i = 0; i < 8; ++i) {
        int nd = m0 + warp * 8 + i;
        if (nd >= Nn) break;
        float* dst = out + (size_t)nd * C_OUT;
#pragma unroll
        for (int p = 0; p < 4; ++p) {
            int cidx = (p < 2) ? (cLo + 2 * p) : (cHi + 2 * (p - 2));
            float2 z = unpack2(acc[i][p]);
            float o0 = fmaxf(z.x + __ldg(&b3[cidx]),     0.0f) * __ldg(&g_s3[cidx])     + __ldg(&g_t3[cidx]);
            float o1 = fmaxf(z.y + __ldg(&b3[cidx + 1]), 0.0f) * __ldg(&g_s3[cidx + 1]) + __ldg(&g_t3[cidx + 1]);
            *(float2*)(dst + cidx) = make_float2(o0, o1);
        }
    }
}

// ---------------------------------------------------------------------------
extern "C" void kernel_launch(void* const* d_in, const int* in_sizes, int n_in,
                              void* d_out, int out_size) {
    const float* x   = (const float*)d_in[0];
    const void*  idx = (const void*)d_in[1];
    const float* W1 = (const float*)d_in[2];  const float* b1 = (const float*)d_in[3];
    const float* g1 = (const float*)d_in[4];  const float* be1= (const float*)d_in[5];
    const float* m1 = (const float*)d_in[6];  const float* v1 = (const float*)d_in[7];
    const float* W2 = (const float*)d_in[8];  const float* b2 = (const float*)d_in[9];
    const float* g2 = (const float*)d_in[10]; const float* be2= (const float*)d_in[11];
    const float* m2 = (const float*)d_in[12]; const float* v2 = (const float*)d_in[13];
    const float* W3 = (const float*)d_in[14]; const float* b3 = (const float*)d_in[15];
    const float* g3 = (const float*)d_in[16]; const float* be3= (const float*)d_in[17];
    const float* m3 = (const float*)d_in[18]; const float* v3 = (const float*)d_in[19];
    float* out = (float*)d_out;

    int Nn = in_sizes[0] / C_IN;
    long long E2 = (long long)in_sizes[1];
    long long E  = E2 >> 1;
    long long EN = E + Nn;

    size_t shmem13 = (size_t)TM * SVS * sizeof(float2) + (size_t)KC * C_OUT * sizeof(float);
    cudaFuncSetAttribute(k1_node_gemm, cudaFuncAttributeMaxDynamicSharedMemorySize, (int)shmem13);
    cudaFuncSetAttribute(k2_edge_mma,  cudaFuncAttributeMaxDynamicSharedMemorySize, SM_TOT);
    cudaFuncSetAttribute(k3_out_gemm,  cudaFuncAttributeMaxDynamicSharedMemorySize, (int)shmem13);

    detect_idx<<<1, 32>>>((const int*)idx);
    decode_idx<<<(int)((E2 + 255) / 256), 256>>>(idx, E2, Nn);

    prep_bn<<<1, C_OUT>>>(g1, be1, m1, v1, W2, b2, g2, be2, m2, v2, g3, be3, m3, v3);
    prep_w<<<(C_IN * 2 * C_OUT + 255) / 256, 256>>>(W1, W2, W3, g1, v1);

    int total = Nn * C_OUT;
    init_agg<<<(total + 255) / 256, 256>>>(total);

    dim3 grid1((Nn + TM - 1) / TM, 2);
    k1_node_gemm<<<grid1, NTHR, shmem13>>>(x, b1, Nn);

    int nblk2 = (int)((EN + 63) / 64);
    k2_edge_mma<<<nblk2, NTHR, SM_TOT>>>(E, Nn);

    k3_out_gemm<<<(Nn + TM - 1) / TM, NTHR, shmem13>>>(b3, out, Nn);
}

// round 13
// speedup vs baseline: 2.2573x; 1.0328x over previous
#include <cuda_runtime.h>
#include <cuda_bf16.h>
#include <math.h>
#include <float.h>
#include <stdint.h>

// ---------------------------------------------------------------------------
// EdgeConv GNN block (plain sm_103-safe: mma.sync bf16 tensor path)
//  k1 (fp32 FFMA2): A = x(W1a-W1b)^T + b1, B = x W1b^T  -> g_AB
//  sort: messages (edges + self loops) counting-sorted by tgt
//  k2 (mma.sync bf16, 3-pass hi/lo): per 64-message sorted tile,
//      V = relu(A[tgt]+B[src]) split hi/lo bf16; W2' (BN1-folded) pre-split;
//      C(fp32) += Vh*Wh + Vh*Wl + Vl*Wh over K=256;
//      epilogue: h2 = BN2(relu(C + c2)) -> smem tile -> per-column run-max
//                scan over sorted rows -> few atomic float max into g_agg
//  k3 (fp32 FFMA2): out = BN3(relu(agg W3^T + b3))
// ---------------------------------------------------------------------------

#define C_IN   128
#define C_OUT  256
#define TM     64
#define KC     64
#define NTHR   256
#define SVS    66
#define HBS    260    // h-tile row stride in floats (bank-stagger)
#define BN_EPS 1e-5f
#define MAXN   20000
#define MAXE   640000
#define MAXM   (MAXE + MAXN)

// ---- static device scratch -------------------------------------------------
static __device__ __align__(128) float g_AB [(size_t)MAXN * 2 * C_OUT];
static __device__ __align__(128) float g_agg[(size_t)MAXN * C_OUT];
static __device__ __align__(128) float g_Wct[C_IN * 2 * C_OUT];
static __device__ __align__(128) float g_W3t[C_OUT * C_OUT];
static __device__ __align__(128) __nv_bfloat16 g_W2h[C_OUT * C_OUT]; // [n][k] hi
static __device__ __align__(128) __nv_bfloat16 g_W2l[C_OUT * C_OUT]; // [n][k] lo
static __device__ __align__(128) float g_c2 [C_OUT];
static __device__ __align__(128) float g_s2 [C_OUT], g_t2[C_OUT];
static __device__ __align__(128) float g_s3 [C_OUT], g_t3[C_OUT];
static __device__ __align__(128) int   g_src[MAXE], g_tgt[MAXE];
static __device__ __align__(128) int   g_osrc[MAXM], g_otgt[MAXM];
static __device__ __align__(128) int   g_cnt[MAXN], g_cur[MAXN];
static __device__ int g_idx64;

// ---- PTX helpers ------------------------------------------------------------
__device__ __forceinline__ unsigned long long fma2(unsigned long long a,
                                                   unsigned long long b,
                                                   unsigned long long c) {
    unsigned long long d;
    asm("fma.rn.f32x2 %0, %1, %2, %3;" : "=l"(d) : "l"(a), "l"(b), "l"(c));
    return d;
}
__device__ __forceinline__ float2 unpack2(unsigned long long u) {
    float2 f;
    asm("mov.b64 {%0, %1}, %2;" : "=f"(f.x), "=f"(f.y) : "l"(u));
    return f;
}
__device__ __forceinline__ void lds_v2u64(unsigned long long& a, unsigned long long& b,
                                          unsigned int addr) {
    asm volatile("ld.shared.v2.u64 {%0, %1}, [%2];" : "=l"(a), "=l"(b) : "r"(addr));
}
__device__ __forceinline__ void atomicMaxF(float* a, float v) {
    int bits = __float_as_int(v);
    if (bits >= 0) atomicMax((int*)a, bits);
    else           atomicMin((unsigned int*)a, (unsigned int)bits);
}
__device__ __forceinline__ uint32_t smem_u32(const void* p) {
    uint32_t a;
    asm("{ .reg .u64 t; cvta.to.shared.u64 t, %1; cvt.u32.u64 %0, t; }"
        : "=r"(a) : "l"(p));
    return a;
}
__device__ __forceinline__ uint32_t pack_bf2(float a, float b) {
    __nv_bfloat162 p = __floats2bfloat162_rn(a, b);
    return *(uint32_t*)&p;
}

#define SWZ(o) ((o) ^ (((o) >> 3) & 0x70))

#define LDSM4(r0, r1, r2, r3, addr) \
    asm volatile("ldmatrix.sync.aligned.m8n8.x4.shared.b16 {%0,%1,%2,%3}, [%4];" \
                 : "=r"(r0), "=r"(r1), "=r"(r2), "=r"(r3) : "r"(addr))

#define MMA_BF16(d, a, b0, b1) \
    asm volatile("mma.sync.aligned.m16n8k16.row.col.f32.bf16.bf16.f32 " \
                 "{%0,%1,%2,%3}, {%4,%5,%6,%7}, {%8,%9}, {%0,%1,%2,%3};" \
                 : "+f"((d)[0]), "+f"((d)[1]), "+f"((d)[2]), "+f"((d)[3]) \
                 : "r"((a)[0]), "r"((a)[1]), "r"((a)[2]), "r"((a)[3]), \
                   "r"(b0), "r"(b1))

// ---- fp32 FFMA2 GEMM inner loop (k1/k3, proven) -----------------------------
__device__ __forceinline__ void gemm_chunk2(unsigned vAddr, unsigned wAddr,
                                            unsigned long long acc[8][4]) {
#pragma unroll 2
    for (int k = 0; k < KC; k += 2) {
        unsigned long long w00a, w00b, w01a, w01b, w10a, w10b, w11a, w11b;
        unsigned wk = wAddr + (unsigned)(k * 1024);
        lds_v2u64(w00a, w00b, wk);
        lds_v2u64(w01a, w01b, wk + 512);
        lds_v2u64(w10a, w10b, wk + 1024);
        lds_v2u64(w11a, w11b, wk + 1536);
#pragma unroll
        for (int i = 0; i < 8; ++i) {
            unsigned long long va, vb;
            lds_v2u64(va, vb, vAddr + (unsigned)(i * (SVS * 8) + k * 8));
            acc[i][0] = fma2(va, w00a, acc[i][0]);
            acc[i][1] = fma2(va, w00b, acc[i][1]);
            acc[i][2] = fma2(va, w01a, acc[i][2]);
            acc[i][3] = fma2(va, w01b, acc[i][3]);
            acc[i][0] = fma2(vb, w10a, acc[i][0]);
            acc[i][1] = fma2(vb, w10b, acc[i][1]);
            acc[i][2] = fma2(vb, w11a, acc[i][2]);
            acc[i][3] = fma2(vb, w11b, acc[i][3]);
        }
    }
}

__device__ __forceinline__ void load_w_chunk(float* sW, const float* __restrict__ gW,
                                             int rowStride, int tid) {
    for (int t = tid; t < KC * (C_OUT / 4); t += NTHR) {
        int kk = t >> 6;
        int c4 = t & 63;
        *(float4*)(sW + kk * C_OUT + (c4 << 2)) =
            *(const float4*)(gW + (size_t)kk * rowStride + (c4 << 2));
    }
}
__device__ __forceinline__ void stage_dup4(float2* d, float4 v) {
    *(float4*)(d)     = make_float4(v.x, v.x, v.y, v.y);
    *(float4*)(d + 2) = make_float4(v.z, v.z, v.w, v.w);
}

// ---- edge index dtype detection + decode ------------------------------------
__global__ void detect_idx(const int* __restrict__ p) {
    if (threadIdx.x == 0) {
        int is64 = 1;
        for (int i = 0; i < 64; ++i)
            if (p[2 * i + 1] != 0) { is64 = 0; break; }
        g_idx64 = is64;
    }
}
__global__ void decode_idx(const void* __restrict__ idxRaw, long long E2, int Nn) {
    long long i = (long long)blockIdx.x * blockDim.x + threadIdx.x;
    if (i >= E2) return;
    int v;
    if (g_idx64) v = (int)((const long long*)idxRaw)[i];
    else         v = ((const int*)idxRaw)[i];
    if (v < 0) v = 0;
    if (v >= Nn) v = Nn - 1;
    long long E = E2 >> 1;
    if (i < E) g_src[i] = v;
    else       g_tgt[i - E] = v;
}

// ---- counting sort by tgt (verified in R6) ----------------------------------
__global__ void hist_zero(int Nn) {
    int i = blockIdx.x * blockDim.x + threadIdx.x;
    if (i < Nn) g_cnt[i] = 0;
}
__global__ void hist_tgt(long long E) {
    long long m = (long long)blockIdx.x * blockDim.x + threadIdx.x;
    if (m < E) atomicAdd(&g_cnt[g_tgt[m]], 1);
}
__global__ void scan_base(int Nn) {     // single CTA, 256 threads
    __shared__ int part[256];
    int th = threadIdx.x;
    int chunk = (Nn + 255) >> 8;
    int lo = th * chunk, hi = lo + chunk; if (hi > Nn) hi = Nn; if (lo > Nn) lo = Nn;
    int s = 0;
    for (int n = lo; n < hi; ++n) s += g_cnt[n] + 1;   // +1 self loop
    part[th] = s;
    __syncthreads();
    if (th == 0) {
        int r = 0;
        for (int i = 0; i < 256; ++i) { int t = part[i]; part[i] = r; r += t; }
    }
    __syncthreads();
    int run = part[th];
    for (int n = lo; n < hi; ++n) { g_cur[n] = run; run += g_cnt[n] + 1; }
}
__global__ void scatter_edges(long long E) {
    long long m = (long long)blockIdx.x * blockDim.x + threadIdx.x;
    if (m >= E) return;
    int t = g_tgt[m];
    int p = atomicAdd(&g_cur[t], 1);
    g_osrc[p] = g_src[m];
    g_otgt[p] = t;
}
__global__ void scatter_loops(int Nn) {
    int n = blockIdx.x * blockDim.x + threadIdx.x;
    if (n >= Nn) return;
    int p = atomicAdd(&g_cur[n], 1);
    g_osrc[p] = n;
    g_otgt[p] = n;
}

// ---- prep kernels -----------------------------------------------------------
__global__ void prep_bn(const float* g1, const float* be1, const float* m1, const float* v1,
                        const float* W2, const float* b2,
                        const float* g2, const float* be2, const float* m2, const float* v2,
                        const float* g3, const float* be3, const float* m3, const float* v3) {
    int c = threadIdx.x;
    float s2 = g2[c] * rsqrtf(v2[c] + BN_EPS);
    g_s2[c] = s2;  g_t2[c] = be2[c] - m2[c] * s2;
    float s3 = g3[c] * rsqrtf(v3[c] + BN_EPS);
    g_s3[c] = s3;  g_t3[c] = be3[c] - m3[c] * s3;
    float acc = b2[c];
    for (int k = 0; k < C_OUT; ++k) {
        float s1 = g1[k] * rsqrtf(v1[k] + BN_EPS);
        float t1 = be1[k] - m1[k] * s1;
        acc += W2[c * C_OUT + k] * t1;
    }
    g_c2[c] = acc;
}

__global__ void prep_w(const float* W1, const float* W2, const float* W3,
                       const float* g1, const float* v1) {
    int i = blockIdx.x * blockDim.x + threadIdx.x;
    if (i < C_IN * 2 * C_OUT) {
        int k = i / (2 * C_OUT), j = i % (2 * C_OUT);
        float val;
        if (j < C_OUT)
            val = W1[j * (2 * C_IN) + k] - W1[j * (2 * C_IN) + C_IN + k];
        else
            val = W1[(j - C_OUT) * (2 * C_IN) + C_IN + k];
        g_Wct[i] = val;
    }
    if (i < C_OUT * C_OUT) {
        int k = i / C_OUT, n = i % C_OUT;
        float s1 = g1[k] * rsqrtf(v1[k] + BN_EPS);
        g_W3t[i] = W3[n * C_OUT + k];                   // [k][n] for k3
        int nn = i / C_OUT, kk = i % C_OUT;
        float s1k = g1[kk] * rsqrtf(v1[kk] + BN_EPS);
        float w = W2[nn * C_OUT + kk] * s1k;
        __nv_bfloat16 hb = __float2bfloat16(w);
        g_W2h[i] = hb;
        g_W2l[i] = __float2bfloat16(w - __bfloat162float(hb));
    }
}

__global__ void init_agg(int total) {
    int i = blockIdx.x * blockDim.x + threadIdx.x;
    if (i < total) g_agg[i] = -FLT_MAX;
}

// ---- kernel 1: node GEMM -> A|B table (fp32 FFMA2) --------------------------
__global__ void __launch_bounds__(NTHR, 2)
k1_node_gemm(const float* __restrict__ x, const float* __restrict__ b1, int Nn) {
    extern __shared__ float sh[];
    float2* sV2 = (float2*)sh;
    float*  sW  = sh + TM * SVS * 2;
    int tid = threadIdx.x;
    int warp = tid >> 5, ng = tid & 31;
    int row = tid >> 2, q = tid & 3;
    int m0 = blockIdx.x * TM;
    int jh = blockIdx.y;
    int node = m0 + row; if (node >= Nn) node = Nn - 1;

    unsigned vAddr = smem_u32(sV2) + (unsigned)(warp * 8 * SVS * 8);
    unsigned wAddr = smem_u32(sW) + (unsigned)(ng * 16);

    unsigned long long acc[8][4];
#pragma unroll
    for (int i = 0; i < 8; ++i)
#pragma unroll
        for (int p = 0; p < 4; ++p) acc[i][p] = 0ull;

    for (int kc = 0; kc < C_IN; kc += KC) {
        load_w_chunk(sW, g_Wct + (size_t)kc * (2 * C_OUT) + jh * C_OUT, 2 * C_OUT, tid);
        const float4* xr = (const float4*)(x + (size_t)node * C_IN + kc) + q * 4;
        float2* d = sV2 + row * SVS + q * 16;
#pragma unroll
        for (int j = 0; j < 4; ++j) stage_dup4(d + j * 4, xr[j]);
        __syncthreads();
        gemm_chunk2(vAddr, wAddr, acc);
        __syncthreads();
    }

    int cLo = ng * 4, cHi = 128 + ng * 4;
#pragma unroll
    for (int i = 0; i < 8; ++i) {
        int nd = m0 + warp * 8 + i;
        if (nd >= Nn) break;
        float* dst = g_AB + (size_t)nd * (2 * C_OUT) + jh * C_OUT;
#pragma unroll
        for (int p = 0; p < 4; ++p) {
            int c = (p < 2) ? (cLo + 2 * p) : (cHi + 2 * (p - 2));
            float2 z = unpack2(acc[i][p]);
            if (jh == 0) { z.x += __ldg(&b1[c]); z.y += __ldg(&b1[c + 1]); }
            *(float2*)(dst + c) = z;
        }
    }
}

// ---- kernel 2: mma.sync bf16 + sorted run-max epilogue ----------------------
// smem byte offsets (h-tile reuses the V/W region after the last MMA sync)
#define SM_TGT   0                    // 64 ints
#define SM_VHI   1024                 // 64 rows x 128B
#define SM_VLO   (SM_VHI + 8192)
#define SM_WHI   (SM_VLO + 8192)      // 256 rows x 128B
#define SM_WLO   (SM_WHI + 32768)
#define SM_TOT   (SM_WLO + 32768)     // 82944 bytes
#define SM_HB    1024                 // h tile: 64 x HBS floats = 66560B

__global__ void __launch_bounds__(NTHR, 2)
k2_edge_mma(long long EN) {
    extern __shared__ char smem[];
    uint32_t sb = smem_u32(smem);
    int tid = threadIdx.x;
    int lane = tid & 31, w = tid >> 5;
    int rg = w & 3, cg = w >> 2;                 // 4 row groups x 2 col halves
    long long m0 = (long long)blockIdx.x * 64;

    int* sTgt = (int*)(smem + SM_TGT);
    if (tid < 64) {
        long long m = m0 + tid;
        sTgt[tid] = (m < EN) ? g_otgt[m] : -1;
    }

    // staging source: thread covers row r, k-quarter q (16 floats per chunk)
    int r = tid >> 2, q = tid & 3;
    long long mr = m0 + r;
    int s = 0, t = 0;
    if (mr < EN) { s = g_osrc[mr]; t = g_otgt[mr]; }
    const float* Arow = g_AB + (size_t)t * (2 * C_OUT);
    const float* Brow = g_AB + (size_t)s * (2 * C_OUT) + C_OUT;

    float c[16][4];
#pragma unroll
    for (int i = 0; i < 16; ++i)
#pragma unroll
        for (int p = 0; p < 4; ++p) c[i][p] = 0.0f;

    for (int kc = 0; kc < C_OUT; kc += 64) {
        // ---- stage V hi/lo: relu(A+B), bf16 split, SW128 swizzled ----------
        {
            const float4* a4 = (const float4*)(Arow + kc) + q * 4;
            const float4* b4 = (const float4*)(Brow + kc) + q * 4;
            uint32_t H[8], L[8];
#pragma unroll
            for (int j = 0; j < 4; ++j) {
                float4 a = a4[j], b = b4[j];
                float u0 = fmaxf(a.x + b.x, 0.0f);
                float u1 = fmaxf(a.y + b.y, 0.0f);
                float u2 = fmaxf(a.z + b.z, 0.0f);
                float u3 = fmaxf(a.w + b.w, 0.0f);
                __nv_bfloat16 h0 = __float2bfloat16(u0), h1 = __float2bfloat16(u1);
                __nv_bfloat16 h2 = __float2bfloat16(u2), h3 = __float2bfloat16(u3);
                H[j * 2 + 0] = pack_bf2(__bfloat162float(h0), __bfloat162float(h1));
                H[j * 2 + 1] = pack_bf2(__bfloat162float(h2), __bfloat162float(h3));
                L[j * 2 + 0] = pack_bf2(u0 - __bfloat162float(h0), u1 - __bfloat162float(h1));
                L[j * 2 + 1] = pack_bf2(u2 - __bfloat162float(h2), u3 - __bfloat162float(h3));
            }
            uint32_t off = (uint32_t)(r * 128 + q * 32);
            *(uint4*)(smem + SM_VHI + SWZ(off))      = make_uint4(H[0], H[1], H[2], H[3]);
            *(uint4*)(smem + SM_VHI + SWZ(off + 16)) = make_uint4(H[4], H[5], H[6], H[7]);
            *(uint4*)(smem + SM_VLO + SWZ(off))      = make_uint4(L[0], L[1], L[2], L[3]);
            *(uint4*)(smem + SM_VLO + SWZ(off + 16)) = make_uint4(L[4], L[5], L[6], L[7]);
        }
        // ---- stage W hi/lo: row n = tid, 128B per chunk --------------------
        {
            const uint4* gh = (const uint4*)((const char*)g_W2h + (size_t)tid * 512 + kc * 2);
            const uint4* gl = (const uint4*)((const char*)g_W2l + (size_t)tid * 512 + kc * 2);
#pragma unroll
            for (int j = 0; j < 8; ++j) {
                uint32_t off = (uint32_t)(tid * 128 + j * 16);
                uint32_t swo = SWZ(off);
                *(uint4*)(smem + SM_WHI + swo) = gh[j];
                *(uint4*)(smem + SM_WLO + swo) = gl[j];
            }
        }
        __syncthreads();

        // ---- compute: 4 k16 steps, 3 passes --------------------------------
#pragma unroll
        for (int ks = 0; ks < 4; ++ks) {
            uint32_t aoff = SWZ((uint32_t)((rg * 16 + (lane & 15)) * 128 +
                                           ks * 32 + (lane >> 4) * 16));
            uint32_t ah[4], al[4];
            LDSM4(ah[0], ah[1], ah[2], ah[3], sb + SM_VHI + aoff);
            LDSM4(al[0], al[1], al[2], al[3], sb + SM_VLO + aoff);
#pragma unroll
            for (int jj = 0; jj < 8; ++jj) {
                uint32_t boff = SWZ((uint32_t)((cg * 128 + jj * 16 + (lane & 15)) * 128 +
                                               ks * 32 + (lane >> 4) * 16));
                uint32_t bh[4], bl[4];
                LDSM4(bh[0], bh[1], bh[2], bh[3], sb + SM_WHI + boff);
                LDSM4(bl[0], bl[1], bl[2], bl[3], sb + SM_WLO + boff);
                MMA_BF16(c[2 * jj],     ah, bh[0], bh[2]);
                MMA_BF16(c[2 * jj + 1], ah, bh[1], bh[3]);
                MMA_BF16(c[2 * jj],     ah, bl[0], bl[2]);
                MMA_BF16(c[2 * jj + 1], ah, bl[1], bl[3]);
                MMA_BF16(c[2 * jj],     al, bh[0], bh[2]);
                MMA_BF16(c[2 * jj + 1], al, bh[1], bh[3]);
            }
        }
        __syncthreads();
    }

    // ---- epilogue 1: h2 = BN2(relu(z + c2)) -> smem h tile -----------------
    float* hbuf = (float*)(smem + SM_HB);
    int r0 = rg * 16 + (lane >> 2), r1 = r0 + 8;
#pragma unroll
    for (int jj = 0; jj < 16; ++jj) {
        int cn = cg * 128 + jj * 8 + (lane & 3) * 2;
        float c2a = __ldg(&g_c2[cn]), c2b = __ldg(&g_c2[cn + 1]);
        float s2a = __ldg(&g_s2[cn]), s2b = __ldg(&g_s2[cn + 1]);
        float t2a = __ldg(&g_t2[cn]), t2b = __ldg(&g_t2[cn + 1]);
        float h00 = fmaxf(c[jj][0] + c2a, 0.0f) * s2a + t2a;
        float h01 = fmaxf(c[jj][1] + c2b, 0.0f) * s2b + t2b;
        float h10 = fmaxf(c[jj][2] + c2a, 0.0f) * s2a + t2a;
        float h11 = fmaxf(c[jj][3] + c2b, 0.0f) * s2b + t2b;
        *(float2*)(hbuf + r0 * HBS + cn) = make_float2(h00, h01);
        *(float2*)(hbuf + r1 * HBS + cn) = make_float2(h10, h11);
    }
    __syncthreads();

    // ---- epilogue 2: per-column run-max scan over sorted rows --------------
    {
        int col = tid;
        float run = -FLT_MAX;
        int curt = sTgt[0];
#pragma unroll 8
        for (int rr = 0; rr < 64; ++rr) {
            int tg = sTgt[rr];
            float v = hbuf[rr * HBS + col];
            if (tg != curt) {
                if (curt >= 0) atomicMaxF(g_agg + (size_t)curt * C_OUT + col, run);
                run = -FLT_MAX;
                curt = tg;
            }
            run = fmaxf(run, v);
        }
        if (curt >= 0) atomicMaxF(g_agg + (size_t)curt * C_OUT + col, run);
    }
}

// ---- kernel 3: out = BN3(relu(agg @ W3^T + b3)) (fp32 FFMA2) ----------------
__global__ void __launch_bounds__(NTHR, 2)
k3_out_gemm(const float* __restrict__ b3, float* __restrict__ out, int Nn) {
    extern __shared__ float sh[];
    float2* sV2 = (float2*)sh;
    float*  sW  = sh + TM * SVS * 2;
    int tid = threadIdx.x;
    int warp = tid >> 5, ng = tid & 31;
    int row = tid >> 2, q = tid & 3;
    int m0 = blockIdx.x * TM;
    int node = m0 + row; if (node >= Nn) node = Nn - 1;

    unsigned vAddr = smem_u32(sV2) + (unsigned)(warp * 8 * SVS * 8);
    unsigned wAddr = smem_u32(sW) + (unsigned)(ng * 16);

    unsigned long long acc[8][4];
#pragma unroll
    for (int i = 0; i < 8; ++i)
#pragma unroll
        for (int p = 0; p < 4; ++p) acc[i][p] = 0ull;

    const float* Ar = g_agg + (size_t)node * C_OUT;
    for (int kc = 0; kc < C_OUT; kc += KC) {
        load_w_chunk(sW, g_W3t + (size_t)kc * C_OUT, C_OUT, tid);
        const float4* ar = (const float4*)(Ar + kc) + q * 4;
        float2* d = sV2 + row * SVS + q * 16;
#pragma unroll
        for (int j = 0; j < 4; ++j) stage_dup4(d + j * 4, ar[j]);
        __syncthreads();
        gemm_chunk2(vAddr, wAddr, acc);
        __syncthreads();
    }

    int cLo = ng * 4, cHi = 128 + ng * 4;
#pragma unroll
    for (int i = 0; i < 8; ++i) {
        int nd = m0 + warp * 8 + i;
        if (nd >= Nn) break;
        float* dst = out + (size_t)nd * C_OUT;
#pragma unroll
        for (int p = 0; p < 4; ++p) {
            int cidx = (p < 2) ? (cLo + 2 * p) : (cHi + 2 * (p - 2));
            float2 z = unpack2(acc[i][p]);
            float o0 = fmaxf(z.x + __ldg(&b3[cidx]),     0.0f) * __ldg(&g_s3[cidx])     + __ldg(&g_t3[cidx]);
            float o1 = fmaxf(z.y + __ldg(&b3[cidx + 1]), 0.0f) * __ldg(&g_s3[cidx + 1]) + __ldg(&g_t3[cidx + 1]);
            *(float2*)(dst + cidx) = make_float2(o0, o1);
        }
    }
}

// ---------------------------------------------------------------------------
extern "C" void kernel_launch(void* const* d_in, const int* in_sizes, int n_in,
                              void* d_out, int out_size) {
    const float* x   = (const float*)d_in[0];
    const void*  idx = (const void*)d_in[1];
    const float* W1 = (const float*)d_in[2];  const float* b1 = (const float*)d_in[3];
    const float* g1 = (const float*)d_in[4];  const float* be1= (const float*)d_in[5];
    const float* m1 = (const float*)d_in[6];  const float* v1 = (const float*)d_in[7];
    const float* W2 = (const float*)d_in[8];  const float* b2 = (const float*)d_in[9];
    const float* g2 = (const float*)d_in[10]; const float* be2= (const float*)d_in[11];
    const float* m2 = (const float*)d_in[12]; const float* v2 = (const float*)d_in[13];
    const float* W3 = (const float*)d_in[14]; const float* b3 = (const float*)d_in[15];
    const float* g3 = (const float*)d_in[16]; const float* be3= (const float*)d_in[17];
    const float* m3 = (const float*)d_in[18]; const float* v3 = (const float*)d_in[19];
    float* out = (float*)d_out;

    int Nn = in_sizes[0] / C_IN;
    long long E2 = (long long)in_sizes[1];
    long long E  = E2 >> 1;
    long long EN = E + Nn;

    size_t shmem13 = (size_t)TM * SVS * sizeof(float2) + (size_t)KC * C_OUT * sizeof(float);
    cudaFuncSetAttribute(k1_node_gemm, cudaFuncAttributeMaxDynamicSharedMemorySize, (int)shmem13);
    cudaFuncSetAttribute(k2_edge_mma,  cudaFuncAttributeMaxDynamicSharedMemorySize, SM_TOT);
    cudaFuncSetAttribute(k3_out_gemm,  cudaFuncAttributeMaxDynamicSharedMemorySize, (int)shmem13);

    detect_idx<<<1, 32>>>((const int*)idx);
    decode_idx<<<(int)((E2 + 255) / 256), 256>>>(idx, E2, Nn);

    hist_zero<<<(Nn + 255) / 256, 256>>>(Nn);
    hist_tgt<<<(int)((E + 255) / 256), 256>>>(E);
    scan_base<<<1, 256>>>(Nn);
    scatter_edges<<<(int)((E + 255) / 256), 256>>>(E);
    scatter_loops<<<(Nn + 255) / 256, 256>>>(Nn);

    prep_bn<<<1, C_OUT>>>(g1, be1, m1, v1, W2, b2, g2, be2, m2, v2, g3, be3, m3, v3);
    prep_w<<<(C_IN * 2 * C_OUT + 255) / 256, 256>>>(W1, W2, W3, g1, v1);

    int total = Nn * C_OUT;
    init_agg<<<(total + 255) / 256, 256>>>(total);

    dim3 grid1((Nn + TM - 1) / TM, 2);
    k1_node_gemm<<<grid1, NTHR, shmem13>>>(x, b1, Nn);

    int nblk2 = (int)((EN + 63) / 64);
    k2_edge_mma<<<nblk2, NTHR, SM_TOT>>>(EN);

    k3_out_gemm<<<(Nn + TM - 1) / TM, NTHR, shmem13>>>(b3, out, Nn);
}

// round 14
// speedup vs baseline: 2.2598x; 1.0011x over previous
#include <cuda_runtime.h>
#include <cuda_bf16.h>
#include <math.h>
#include <float.h>
#include <stdint.h>

// ---------------------------------------------------------------------------
// EdgeConv GNN block (plain sm_103-safe: mma.sync bf16 tensor path)
//  k1 (fp32 FFMA2): A = x(W1a-W1b)^T + b1, B = x W1b^T  -> g_AB
//  sort: messages (edges + self loops) counting-sorted by tgt
//  k2 (mma.sync bf16, 3-pass hi/lo): per 64-message sorted tile,
//      V = relu(A[tgt]+B[src]) split hi/lo bf16; W2' (BN1-folded) pre-split;
//      C(fp32) += Vh*Wh + Vh*Wl + Vl*Wh over K=256;
//      epilogue: h2 = BN2(relu(C + c2)) -> smem tile -> per-column run-max
//                scan over sorted rows -> few atomic float max into g_agg
//  k3 (fp32 FFMA2): out = BN3(relu(agg W3^T + b3))
// ---------------------------------------------------------------------------

#define C_IN   128
#define C_OUT  256
#define TM     64
#define KC     64
#define NTHR   256
#define SVS    66
#define HBS    260    // h-tile row stride in floats (bank-stagger)
#define BN_EPS 1e-5f
#define MAXN   20000
#define MAXE   640000
#define MAXM   (MAXE + MAXN)

// ---- static device scratch -------------------------------------------------
static __device__ __align__(128) float g_AB [(size_t)MAXN * 2 * C_OUT];
static __device__ __align__(128) float g_agg[(size_t)MAXN * C_OUT];
static __device__ __align__(128) float g_Wct[C_IN * 2 * C_OUT];
static __device__ __align__(128) float g_W3t[C_OUT * C_OUT];
static __device__ __align__(128) __nv_bfloat16 g_W2h[C_OUT * C_OUT]; // [n][k] hi
static __device__ __align__(128) __nv_bfloat16 g_W2l[C_OUT * C_OUT]; // [n][k] lo
static __device__ __align__(128) float g_c2 [C_OUT];
static __device__ __align__(128) float g_s2 [C_OUT], g_t2[C_OUT];
static __device__ __align__(128) float g_s3 [C_OUT], g_t3[C_OUT];
static __device__ __align__(128) int   g_src[MAXE], g_tgt[MAXE];
static __device__ __align__(128) int   g_osrc[MAXM], g_otgt[MAXM];
static __device__ __align__(128) int   g_cnt[MAXN], g_cur[MAXN];
static __device__ int g_idx64;

// ---- PTX helpers ------------------------------------------------------------
__device__ __forceinline__ unsigned long long fma2(unsigned long long a,
                                                   unsigned long long b,
                                                   unsigned long long c) {
    unsigned long long d;
    asm("fma.rn.f32x2 %0, %1, %2, %3;" : "=l"(d) : "l"(a), "l"(b), "l"(c));
    return d;
}
__device__ __forceinline__ float2 unpack2(unsigned long long u) {
    float2 f;
    asm("mov.b64 {%0, %1}, %2;" : "=f"(f.x), "=f"(f.y) : "l"(u));
    return f;
}
__device__ __forceinline__ void lds_v2u64(unsigned long long& a, unsigned long long& b,
                                          unsigned int addr) {
    asm volatile("ld.shared.v2.u64 {%0, %1}, [%2];" : "=l"(a), "=l"(b) : "r"(addr));
}
__device__ __forceinline__ void atomicMaxF(float* a, float v) {
    int bits = __float_as_int(v);
    if (bits >= 0) atomicMax((int*)a, bits);
    else           atomicMin((unsigned int*)a, (unsigned int)bits);
}
__device__ __forceinline__ uint32_t smem_u32(const void* p) {
    uint32_t a;
    asm("{ .reg .u64 t; cvta.to.shared.u64 t, %1; cvt.u32.u64 %0, t; }"
        : "=r"(a) : "l"(p));
    return a;
}
__device__ __forceinline__ uint32_t pack_bf2(float a, float b) {
    __nv_bfloat162 p = __floats2bfloat162_rn(a, b);
    return *(uint32_t*)&p;
}

#define SWZ(o) ((o) ^ (((o) >> 3) & 0x70))

#define LDSM4(r0, r1, r2, r3, addr) \
    asm volatile("ldmatrix.sync.aligned.m8n8.x4.shared.b16 {%0,%1,%2,%3}, [%4];" \
                 : "=r"(r0), "=r"(r1), "=r"(r2), "=r"(r3) : "r"(addr))

#define MMA_BF16(d, a, b0, b1) \
    asm volatile("mma.sync.aligned.m16n8k16.row.col.f32.bf16.bf16.f32 " \
                 "{%0,%1,%2,%3}, {%4,%5,%6,%7}, {%8,%9}, {%0,%1,%2,%3};" \
                 : "+f"((d)[0]), "+f"((d)[1]), "+f"((d)[2]), "+f"((d)[3]) \
                 : "r"((a)[0]), "r"((a)[1]), "r"((a)[2]), "r"((a)[3]), \
                   "r"(b0), "r"(b1))

// ---- fp32 FFMA2 GEMM inner loop (k1/k3, proven) -----------------------------
__device__ __forceinline__ void gemm_chunk2(unsigned vAddr, unsigned wAddr,
                                            unsigned long long acc[8][4]) {
#pragma unroll 2
    for (int k = 0; k < KC; k += 2) {
        unsigned long long w00a, w00b, w01a, w01b, w10a, w10b, w11a, w11b;
        unsigned wk = wAddr + (unsigned)(k * 1024);
        lds_v2u64(w00a, w00b, wk);
        lds_v2u64(w01a, w01b, wk + 512);
        lds_v2u64(w10a, w10b, wk + 1024);
        lds_v2u64(w11a, w11b, wk + 1536);
#pragma unroll
        for (int i = 0; i < 8; ++i) {
            unsigned long long va, vb;
            lds_v2u64(va, vb, vAddr + (unsigned)(i * (SVS * 8) + k * 8));
            acc[i][0] = fma2(va, w00a, acc[i][0]);
            acc[i][1] = fma2(va, w00b, acc[i][1]);
            acc[i][2] = fma2(va, w01a, acc[i][2]);
            acc[i][3] = fma2(va, w01b, acc[i][3]);
            acc[i][0] = fma2(vb, w10a, acc[i][0]);
            acc[i][1] = fma2(vb, w10b, acc[i][1]);
            acc[i][2] = fma2(vb, w11a, acc[i][2]);
            acc[i][3] = fma2(vb, w11b, acc[i][3]);
        }
    }
}

__device__ __forceinline__ void load_w_chunk(float* sW, const float* __restrict__ gW,
                                             int rowStride, int tid) {
    for (int t = tid; t < KC * (C_OUT / 4); t += NTHR) {
        int kk = t >> 6;
        int c4 = t & 63;
        *(float4*)(sW + kk * C_OUT + (c4 << 2)) =
            *(const float4*)(gW + (size_t)kk * rowStride + (c4 << 2));
    }
}
__device__ __forceinline__ void stage_dup4(float2* d, float4 v) {
    *(float4*)(d)     = make_float4(v.x, v.x, v.y, v.y);
    *(float4*)(d + 2) = make_float4(v.z, v.z, v.w, v.w);
}

// ---- edge index dtype detection + decode ------------------------------------
__global__ void detect_idx(const int* __restrict__ p) {
    if (threadIdx.x == 0) {
        int is64 = 1;
        for (int i = 0; i < 64; ++i)
            if (p[2 * i + 1] != 0) { is64 = 0; break; }
        g_idx64 = is64;
    }
}
__global__ void decode_idx(const void* __restrict__ idxRaw, long long E2, int Nn) {
    long long i = (long long)blockIdx.x * blockDim.x + threadIdx.x;
    if (i >= E2) return;
    int v;
    if (g_idx64) v = (int)((const long long*)idxRaw)[i];
    else         v = ((const int*)idxRaw)[i];
    if (v < 0) v = 0;
    if (v >= Nn) v = Nn - 1;
    long long E = E2 >> 1;
    if (i < E) g_src[i] = v;
    else       g_tgt[i - E] = v;
}

// ---- counting sort by tgt (verified in R6) ----------------------------------
__global__ void hist_zero(int Nn) {
    int i = blockIdx.x * blockDim.x + threadIdx.x;
    if (i < Nn) g_cnt[i] = 0;
}
__global__ void hist_tgt(long long E) {
    long long m = (long long)blockIdx.x * blockDim.x + threadIdx.x;
    if (m < E) atomicAdd(&g_cnt[g_tgt[m]], 1);
}
__global__ void scan_base(int Nn) {     // single CTA, 256 threads
    __shared__ int part[256];
    int th = threadIdx.x;
    int chunk = (Nn + 255) >> 8;
    int lo = th * chunk, hi = lo + chunk; if (hi > Nn) hi = Nn; if (lo > Nn) lo = Nn;
    int s = 0;
    for (int n = lo; n < hi; ++n) s += g_cnt[n] + 1;   // +1 self loop
    part[th] = s;
    __syncthreads();
    if (th == 0) {
        int r = 0;
        for (int i = 0; i < 256; ++i) { int t = part[i]; part[i] = r; r += t; }
    }
    __syncthreads();
    int run = part[th];
    for (int n = lo; n < hi; ++n) { g_cur[n] = run; run += g_cnt[n] + 1; }
}
__global__ void scatter_edges(long long E) {
    long long m = (long long)blockIdx.x * blockDim.x + threadIdx.x;
    if (m >= E) return;
    int t = g_tgt[m];
    int p = atomicAdd(&g_cur[t], 1);
    g_osrc[p] = g_src[m];
    g_otgt[p] = t;
}
__global__ void scatter_loops(int Nn) {
    int n = blockIdx.x * blockDim.x + threadIdx.x;
    if (n >= Nn) return;
    int p = atomicAdd(&g_cur[n], 1);
    g_osrc[p] = n;
    g_otgt[p] = n;
}

// ---- prep kernels -----------------------------------------------------------
__global__ void prep_bn(const float* g1, const float* be1, const float* m1, const float* v1,
                        const float* W2, const float* b2,
                        const float* g2, const float* be2, const float* m2, const float* v2,
                        const float* g3, const float* be3, const float* m3, const float* v3) {
    int c = threadIdx.x;
    float s2 = g2[c] * rsqrtf(v2[c] + BN_EPS);
    g_s2[c] = s2;  g_t2[c] = be2[c] - m2[c] * s2;
    float s3 = g3[c] * rsqrtf(v3[c] + BN_EPS);
    g_s3[c] = s3;  g_t3[c] = be3[c] - m3[c] * s3;
    float acc = b2[c];
    for (int k = 0; k < C_OUT; ++k) {
        float s1 = g1[k] * rsqrtf(v1[k] + BN_EPS);
        float t1 = be1[k] - m1[k] * s1;
        acc += W2[c * C_OUT + k] * t1;
    }
    g_c2[c] = acc;
}

__global__ void prep_w(const float* W1, const float* W2, const float* W3,
                       const float* g1, const float* v1) {
    int i = blockIdx.x * blockDim.x + threadIdx.x;
    if (i < C_IN * 2 * C_OUT) {
        int k = i / (2 * C_OUT), j = i % (2 * C_OUT);
        float val;
        if (j < C_OUT)
            val = W1[j * (2 * C_IN) + k] - W1[j * (2 * C_IN) + C_IN + k];
        else
            val = W1[(j - C_OUT) * (2 * C_IN) + C_IN + k];
        g_Wct[i] = val;
    }
    if (i < C_OUT * C_OUT) {
        int k = i / C_OUT, n = i % C_OUT;
        float s1 = g1[k] * rsqrtf(v1[k] + BN_EPS);
        g_W3t[i] = W3[n * C_OUT + k];                   // [k][n] for k3
        int nn = i / C_OUT, kk = i % C_OUT;
        float s1k = g1[kk] * rsqrtf(v1[kk] + BN_EPS);
        float w = W2[nn * C_OUT + kk] * s1k;
        __nv_bfloat16 hb = __float2bfloat16(w);
        g_W2h[i] = hb;
        g_W2l[i] = __float2bfloat16(w - __bfloat162float(hb));
    }
}

__global__ void init_agg(int total) {
    int i = blockIdx.x * blockDim.x + threadIdx.x;
    if (i < total) g_agg[i] = -FLT_MAX;
}

// ---- kernel 1: node GEMM -> A|B table (fp32 FFMA2) --------------------------
__global__ void __launch_bounds__(NTHR, 2)
k1_node_gemm(const float* __restrict__ x, const float* __restrict__ b1, int Nn) {
    extern __shared__ float sh[];
    float2* sV2 = (float2*)sh;
    float*  sW  = sh + TM * SVS * 2;
    int tid = threadIdx.x;
    int warp = tid >> 5, ng = tid & 31;
    int row = tid >> 2, q = tid & 3;
    int m0 = blockIdx.x * TM;
    int jh = blockIdx.y;
    int node = m0 + row; if (node >= Nn) node = Nn - 1;

    unsigned vAddr = smem_u32(sV2) + (unsigned)(warp * 8 * SVS * 8);
    unsigned wAddr = smem_u32(sW) + (unsigned)(ng * 16);

    unsigned long long acc[8][4];
#pragma unroll
    for (int i = 0; i < 8; ++i)
#pragma unroll
        for (int p = 0; p < 4; ++p) acc[i][p] = 0ull;

    for (int kc = 0; kc < C_IN; kc += KC) {
        load_w_chunk(sW, g_Wct + (size_t)kc * (2 * C_OUT) + jh * C_OUT, 2 * C_OUT, tid);
        const float4* xr = (const float4*)(x + (size_t)node * C_IN + kc) + q * 4;
        float2* d = sV2 + row * SVS + q * 16;
#pragma unroll
        for (int j = 0; j < 4; ++j) stage_dup4(d + j * 4, xr[j]);
        __syncthreads();
        gemm_chunk2(vAddr, wAddr, acc);
        __syncthreads();
    }

    int cLo = ng * 4, cHi = 128 + ng * 4;
#pragma unroll
    for (int i = 0; i < 8; ++i) {
        int nd = m0 + warp * 8 + i;
        if (nd >= Nn) break;
        float* dst = g_AB + (size_t)nd * (2 * C_OUT) + jh * C_OUT;
#pragma unroll
        for (int p = 0; p < 4; ++p) {
            int c = (p < 2) ? (cLo + 2 * p) : (cHi + 2 * (p - 2));
            float2 z = unpack2(acc[i][p]);
            if (jh == 0) { z.x += __ldg(&b1[c]); z.y += __ldg(&b1[c + 1]); }
            *(float2*)(dst + c) = z;
        }
    }
}

// ---- kernel 2: mma.sync bf16 + sorted run-max epilogue ----------------------
// smem byte offsets (h-tile reuses the V/W region after the last MMA sync)
#define SM_TGT   0                    // 64 ints
#define SM_VHI   1024                 // 64 rows x 128B
#define SM_VLO   (SM_VHI + 8192)
#define SM_WHI   (SM_VLO + 8192)      // 256 rows x 128B
#define SM_WLO   (SM_WHI + 32768)
#define SM_TOT   (SM_WLO + 32768)     // 82944 bytes
#define SM_HB    1024                 // h tile: 64 x HBS floats = 66560B

__global__ void __launch_bounds__(NTHR, 2)
k2_edge_mma(long long EN) {
    extern __shared__ char smem[];
    uint32_t sb = smem_u32(smem);
    int tid = threadIdx.x;
    int lane = tid & 31, w = tid >> 5;
    int rg = w & 3, cg = w >> 2;                 // 4 row groups x 2 col halves
    long long m0 = (long long)blockIdx.x * 64;

    int* sTgt = (int*)(smem + SM_TGT);
    if (tid < 64) {
        long long m = m0 + tid;
        sTgt[tid] = (m < EN) ? g_otgt[m] : -1;
    }

    // staging source: thread covers row r, k-quarter q (16 floats per chunk)
    int r = tid >> 2, q = tid & 3;
    long long mr = m0 + r;
    int s = 0, t = 0;
    if (mr < EN) { s = g_osrc[mr]; t = g_otgt[mr]; }
    const float* Arow = g_AB + (size_t)t * (2 * C_OUT);
    const float* Brow = g_AB + (size_t)s * (2 * C_OUT) + C_OUT;

    float c[16][4];
#pragma unroll
    for (int i = 0; i < 16; ++i)
#pragma unroll
        for (int p = 0; p < 4; ++p) c[i][p] = 0.0f;

    for (int kc = 0; kc < C_OUT; kc += 64) {
        // ---- stage V hi/lo: relu(A+B), bf16 split, SW128 swizzled ----------
        {
            const float4* a4 = (const float4*)(Arow + kc) + q * 4;
            const float4* b4 = (const float4*)(Brow + kc) + q * 4;
            uint32_t H[8], L[8];
#pragma unroll
            for (int j = 0; j < 4; ++j) {
                float4 a = a4[j], b = b4[j];
                float u0 = fmaxf(a.x + b.x, 0.0f);
                float u1 = fmaxf(a.y + b.y, 0.0f);
                float u2 = fmaxf(a.z + b.z, 0.0f);
                float u3 = fmaxf(a.w + b.w, 0.0f);
                __nv_bfloat16 h0 = __float2bfloat16(u0), h1 = __float2bfloat16(u1);
                __nv_bfloat16 h2 = __float2bfloat16(u2), h3 = __float2bfloat16(u3);
                H[j * 2 + 0] = pack_bf2(__bfloat162float(h0), __bfloat162float(h1));
                H[j * 2 + 1] = pack_bf2(__bfloat162float(h2), __bfloat162float(h3));
                L[j * 2 + 0] = pack_bf2(u0 - __bfloat162float(h0), u1 - __bfloat162float(h1));
                L[j * 2 + 1] = pack_bf2(u2 - __bfloat162float(h2), u3 - __bfloat162float(h3));
            }
            uint32_t off = (uint32_t)(r * 128 + q * 32);
            *(uint4*)(smem + SM_VHI + SWZ(off))      = make_uint4(H[0], H[1], H[2], H[3]);
            *(uint4*)(smem + SM_VHI + SWZ(off + 16)) = make_uint4(H[4], H[5], H[6], H[7]);
            *(uint4*)(smem + SM_VLO + SWZ(off))      = make_uint4(L[0], L[1], L[2], L[3]);
            *(uint4*)(smem + SM_VLO + SWZ(off + 16)) = make_uint4(L[4], L[5], L[6], L[7]);
        }
        // ---- stage W hi/lo: row n = tid, 128B per chunk --------------------
        {
            const uint4* gh = (const uint4*)((const char*)g_W2h + (size_t)tid * 512 + kc * 2);
            const uint4* gl = (const uint4*)((const char*)g_W2l + (size_t)tid * 512 + kc * 2);
#pragma unroll
            for (int j = 0; j < 8; ++j) {
                uint32_t off = (uint32_t)(tid * 128 + j * 16);
                uint32_t swo = SWZ(off);
                *(uint4*)(smem + SM_WHI + swo) = gh[j];
                *(uint4*)(smem + SM_WLO + swo) = gl[j];
            }
        }
        __syncthreads();

        // ---- compute: 4 k16 steps, 3 passes --------------------------------
#pragma unroll
        for (int ks = 0; ks < 4; ++ks) {
            uint32_t aoff = SWZ((uint32_t)((rg * 16 + (lane & 15)) * 128 +
                                           ks * 32 + (lane >> 4) * 16));
            uint32_t ah[4], al[4];
            LDSM4(ah[0], ah[1], ah[2], ah[3], sb + SM_VHI + aoff);
            LDSM4(al[0], al[1], al[2], al[3], sb + SM_VLO + aoff);
#pragma unroll
            for (int jj = 0; jj < 8; ++jj) {
                uint32_t boff = SWZ((uint32_t)((cg * 128 + jj * 16 + (lane & 15)) * 128 +
                                               ks * 32 + (lane >> 4) * 16));
                uint32_t bh[4], bl[4];
                LDSM4(bh[0], bh[1], bh[2], bh[3], sb + SM_WHI + boff);
                LDSM4(bl[0], bl[1], bl[2], bl[3], sb + SM_WLO + boff);
                MMA_BF16(c[2 * jj],     ah, bh[0], bh[2]);
                MMA_BF16(c[2 * jj + 1], ah, bh[1], bh[3]);
                MMA_BF16(c[2 * jj],     ah, bl[0], bl[2]);
                MMA_BF16(c[2 * jj + 1], ah, bl[1], bl[3]);
                MMA_BF16(c[2 * jj],     al, bh[0], bh[2]);
                MMA_BF16(c[2 * jj + 1], al, bh[1], bh[3]);
            }
        }
        __syncthreads();
    }

    // ---- epilogue 1: h2 = BN2(relu(z + c2)) -> smem h tile -----------------
    float* hbuf = (float*)(smem + SM_HB);
    int r0 = rg * 16 + (lane >> 2), r1 = r0 + 8;
#pragma unroll
    for (int jj = 0; jj < 16; ++jj) {
        int cn = cg * 128 + jj * 8 + (lane & 3) * 2;
        float c2a = __ldg(&g_c2[cn]), c2b = __ldg(&g_c2[cn + 1]);
        float s2a = __ldg(&g_s2[cn]), s2b = __ldg(&g_s2[cn + 1]);
        float t2a = __ldg(&g_t2[cn]), t2b = __ldg(&g_t2[cn + 1]);
        float h00 = fmaxf(c[jj][0] + c2a, 0.0f) * s2a + t2a;
        float h01 = fmaxf(c[jj][1] + c2b, 0.0f) * s2b + t2b;
        float h10 = fmaxf(c[jj][2] + c2a, 0.0f) * s2a + t2a;
        float h11 = fmaxf(c[jj][3] + c2b, 0.0f) * s2b + t2b;
        *(float2*)(hbuf + r0 * HBS + cn) = make_float2(h00, h01);
        *(float2*)(hbuf + r1 * HBS + cn) = make_float2(h10, h11);
    }
    __syncthreads();

    // ---- epilogue 2: per-column run-max scan over sorted rows --------------
    {
        int col = tid;
        float run = -FLT_MAX;
        int curt = sTgt[0];
#pragma unroll 8
        for (int rr = 0; rr < 64; ++rr) {
            int tg = sTgt[rr];
            float v = hbuf[rr * HBS + col];
            if (tg != curt) {
                if (curt >= 0) atomicMaxF(g_agg + (size_t)curt * C_OUT + col, run);
                run = -FLT_MAX;
                curt = tg;
            }
            run = fmaxf(run, v);
        }
        if (curt >= 0) atomicMaxF(g_agg + (size_t)curt * C_OUT + col, run);
    }
}

// ---- kernel 3: out = BN3(relu(agg @ W3^T + b3)) (fp32 FFMA2) ----------------
__global__ void __launch_bounds__(NTHR, 2)
k3_out_gemm(const float* __restrict__ b3, float* __restrict__ out, int Nn) {
    extern __shared__ float sh[];
    float2* sV2 = (float2*)sh;
    float*  sW  = sh + TM * SVS * 2;
    int tid = threadIdx.x;
    int warp = tid >> 5, ng = tid & 31;
    int row = tid >> 2, q = tid & 3;
    int m0 = blockIdx.x * TM;
    int node = m0 + row; if (node >= Nn) node = Nn - 1;

    unsigned vAddr = smem_u32(sV2) + (unsigned)(warp * 8 * SVS * 8);
    unsigned wAddr = smem_u32(sW) + (unsigned)(ng * 16);

    unsigned long long acc[8][4];
#pragma unroll
    for (int i = 0; i < 8; ++i)
#pragma unroll
        for (int p = 0; p < 4; ++p) acc[i][p] = 0ull;

    const float* Ar = g_agg + (size_t)node * C_OUT;
    for (int kc = 0; kc < C_OUT; kc += KC) {
        load_w_chunk(sW, g_W3t + (size_t)kc * C_OUT, C_OUT, tid);
        const float4* ar = (const float4*)(Ar + kc) + q * 4;
        float2* d = sV2 + row * SVS + q * 16;
#pragma unroll
        for (int j = 0; j < 4; ++j) stage_dup4(d + j * 4, ar[j]);
        __syncthreads();
        gemm_chunk2(vAddr, wAddr, acc);
        __syncthreads();
    }

    int cLo = ng * 4, cHi = 128 + ng * 4;
#pragma unroll
    for (int i = 0; i < 8; ++i) {
        int nd = m0 + warp * 8 + i;
        if (nd >= Nn) break;
        float* dst = out + (size_t)nd * C_OUT;
#pragma unroll
        for (int p = 0; p < 4; ++p) {
            int cidx = (p < 2) ? (cLo + 2 * p) : (cHi + 2 * (p - 2));
            float2 z = unpack2(acc[i][p]);
            float o0 = fmaxf(z.x + __ldg(&b3[cidx]),     0.0f) * __ldg(&g_s3[cidx])     + __ldg(&g_t3[cidx]);
            float o1 = fmaxf(z.y + __ldg(&b3[cidx + 1]), 0.0f) * __ldg(&g_s3[cidx + 1]) + __ldg(&g_t3[cidx + 1]);
            *(float2*)(dst + cidx) = make_float2(o0, o1);
        }
    }
}

// ---------------------------------------------------------------------------
extern "C" void kernel_launch(void* const* d_in, const int* in_sizes, int n_in,
                              void* d_out, int out_size) {
    const float* x   = (const float*)d_in[0];
    const void*  idx = (const void*)d_in[1];
    const float* W1 = (const float*)d_in[2];  const float* b1 = (const float*)d_in[3];
    const float* g1 = (const float*)d_in[4];  const float* be1= (const float*)d_in[5];
    const float* m1 = (const float*)d_in[6];  const float* v1 = (const float*)d_in[7];
    const float* W2 = (const float*)d_in[8];  const float* b2 = (const float*)d_in[9];
    const float* g2 = (const float*)d_in[10]; const float* be2= (const float*)d_in[11];
    const float* m2 = (const float*)d_in[12]; const float* v2 = (const float*)d_in[13];
    const float* W3 = (const float*)d_in[14]; const float* b3 = (const float*)d_in[15];
    const float* g3 = (const float*)d_in[16]; const float* be3= (const float*)d_in[17];
    const float* m3 = (const float*)d_in[18]; const float* v3 = (const float*)d_in[19];
    float* out = (float*)d_out;

    int Nn = in_sizes[0] / C_IN;
    long long E2 = (long long)in_sizes[1];
    long long E  = E2 >> 1;
    long long EN = E + Nn;

    size_t shmem13 = (size_t)TM * SVS * sizeof(float2) + (size_t)KC * C_OUT * sizeof(float);
    cudaFuncSetAttribute(k1_node_gemm, cudaFuncAttributeMaxDynamicSharedMemorySize, (int)shmem13);
    cudaFuncSetAttribute(k2_edge_mma,  cudaFuncAttributeMaxDynamicSharedMemorySize, SM_TOT);
    cudaFuncSetAttribute(k3_out_gemm,  cudaFuncAttributeMaxDynamicSharedMemorySize, (int)shmem13);

    detect_idx<<<1, 32>>>((const int*)idx);
    decode_idx<<<(int)((E2 + 255) / 256), 256>>>(idx, E2, Nn);

    hist_zero<<<(Nn + 255) / 256, 256>>>(Nn);
    hist_tgt<<<(int)((E + 255) / 256), 256>>>(E);
    scan_base<<<1, 256>>>(Nn);
    scatter_edges<<<(int)((E + 255) / 256), 256>>>(E);
    scatter_loops<<<(Nn + 255) / 256, 256>>>(Nn);

    prep_bn<<<1, C_OUT>>>(g1, be1, m1, v1, W2, b2, g2, be2, m2, v2, g3, be3, m3, v3);
    prep_w<<<(C_IN * 2 * C_OUT + 255) / 256, 256>>>(W1, W2, W3, g1, v1);

    int total = Nn * C_OUT;
    init_agg<<<(total + 255) / 256, 256>>>(total);

    dim3 grid1((Nn + TM - 1) / TM, 2);
    k1_node_gemm<<<grid1, NTHR, shmem13>>>(x, b1, Nn);

    int nblk2 = (int)((EN + 63) / 64);
    k2_edge_mma<<<nblk2, NTHR, SM_TOT>>>(EN);

    k3_out_gemm<<<(Nn + TM - 1) / TM, NTHR, shmem13>>>(b3, out, Nn);
}